// round 10
// baseline (speedup 1.0000x reference)
#include <cuda_runtime.h>
#include <math.h>

#define NB 4
#define CIN 3
#define NC 64
#define H0 256
#define W0 256
#define NPIX0 (H0*W0)
#define HP 264
#define NP (HP*HP)      /* 69696 */
#define NR 64
#define NM 32
#define SPW (64*64*32*32)
#define INV_HP (1.0f/264.0f)

typedef unsigned long long u64;

// ---------------- f32x2 packed-FMA helpers -----------------------------------
__device__ __forceinline__ u64 pk(float lo, float hi) {
    u64 r; asm("mov.b64 %0, {%1, %2};" : "=l"(r) : "f"(lo), "f"(hi)); return r;
}
__device__ __forceinline__ u64 pkdup(float v) { return pk(v, v); }
__device__ __forceinline__ float2 up(u64 v) {
    float lo, hi; asm("mov.b64 {%0, %1}, %2;" : "=f"(lo), "=f"(hi) : "l"(v));
    return make_float2(lo, hi);
}
__device__ __forceinline__ u64 f2fma(u64 a, u64 b, u64 c) {
    u64 d; asm("fma.rn.f32x2 %0, %1, %2, %3;" : "=l"(d) : "l"(a), "l"(b), "l"(c)); return d;
}
__device__ __forceinline__ u64 f2add(u64 a, u64 b) {
    u64 d; asm("add.rn.f32x2 %0, %1, %2;" : "=l"(d) : "l"(a), "l"(b)); return d;
}

// ---------------- scratch ----------------------------------------------------
__device__ float  g_x  [NB*NC*NP];
__device__ float  g_hbr[NB*NC*NP];
__device__ float2 g_T1 [NB*NC*33*HP];
__device__ float2 g_xf [NB*NC*NR*NM];
__device__ float2 g_of [NB*NC*NR*NM];
__device__ float2 g_Fy [NR*HP];
__device__ float2 g_Fx [NM*HP];
__device__ float2 g_FxT[HP*NM];
__device__ float  g_Fyc[33*HP];
__device__ float  g_Fys[33*HP];
__device__ float  g_WfT[3*64*128];
__device__ float  g_W3T[3*128*64];
__device__ float  g_bf [3*128];

__device__ __forceinline__ float gelu_exact(float v) {
    return 0.5f * v * (1.0f + erff(v * 0.70710678118654752440f));
}

// ---------------- init --------------------------------------------------------
__global__ void k_tables() {
    int idx = blockIdx.x * 256 + threadIdx.x;
    if (idx < NR*HP) {
        int r = idx / HP, y = idx % HP;
        int ky = (r < 32) ? r : r + 200;
        int m = (ky * y) % HP;
        double a = 6.283185307179586 * (double)m / (double)HP;
        float2 f = make_float2((float)cos(a), (float)(-sin(a)));
        g_Fy[idx] = f;
        if (r <= 32) { g_Fyc[r*HP + y] = f.x; g_Fys[r*HP + y] = f.y; }
    } else if (idx < NR*HP + NM*HP) {
        int j = idx - NR*HP;
        int k = j / HP, xx = j % HP;
        int m = (k * xx) % HP;
        double a = 6.283185307179586 * (double)m / (double)HP;
        float2 f = make_float2((float)cos(a), (float)(-sin(a)));
        g_Fx[j] = f;
        g_FxT[xx*NM + k] = f;
    }
}

__global__ void k_wfuse(const float* __restrict__ cw,  const float* __restrict__ cb,
                        const float* __restrict__ m1w, const float* __restrict__ m1b,
                        const float* __restrict__ m2w) {
    int idx = blockIdx.x * 256 + threadIdx.x;
    if (idx < 3*8192) {
        int L = idx / 8192, r = idx % 8192, k = r >> 7, o = r & 127;
        const float* W2 = m1w + L*8192;
        const float* W1 = cw  + L*4096;
        double s = 0.0;
        for (int j = 0; j < 64; j++) s += (double)W2[o*64 + j] * (double)W1[j*64 + k];
        g_WfT[idx] = (float)s;
    } else if (idx < 6*8192) {
        int i = idx - 3*8192;
        int L = i / 8192, r = i % 8192, k = r >> 6, o = r & 63;
        g_W3T[i] = m2w[L*8192 + o*128 + k];
    } else if (idx < 6*8192 + 384) {
        int i = idx - 6*8192;
        int L = i / 128, o = i % 128;
        const float* W2 = m1w + L*8192;
        double s = (double)m1b[L*128 + o];
        for (int j = 0; j < 64; j++) s += (double)W2[o*64 + j] * (double)cb[L*64 + j];
        g_bf[i] = (float)s;
    }
}

// zero only the right/bottom padding bands
__global__ void k_zero_pad() {
    int idx = blockIdx.x * 256 + threadIdx.x;   // 256 images x 4160 px
    int img = idx / 4160, r = idx % 4160;
    int row, col;
    if (r < 2048) { row = r >> 3; col = 256 + (r & 7); }
    else          { int rr = r - 2048; row = 256 + rr / HP; col = rr % HP; }
    g_x[img*NP + row*HP + col] = 0.0f;
}

// ---------------- lift: 5 -> 32 (GELU) -> 64 (round-8 proven scalar) --------
__global__ void __launch_bounds__(256) k_lift(
    const float* __restrict__ x,
    const float* __restrict__ w1, const float* __restrict__ b1,
    const float* __restrict__ w2, const float* __restrict__ b2)
{
    __shared__ float sw1[32*5], sb1[32], sw2[64*32], sb2[64];
    for (int i = threadIdx.x; i < 160;  i += 256) sw1[i] = w1[i];
    for (int i = threadIdx.x; i < 32;   i += 256) sb1[i] = b1[i];
    for (int i = threadIdx.x; i < 2048; i += 256) sw2[i] = w2[i];
    for (int i = threadIdx.x; i < 64;   i += 256) sb2[i] = b2[i];
    __syncthreads();
    int b = blockIdx.y;
    int p = blockIdx.x * 256 + threadIdx.x;
    int i = p >> 8, j = p & 255;
    float f[5];
    f[0] = x[(b*CIN + 0)*NPIX0 + p];
    f[1] = x[(b*CIN + 1)*NPIX0 + p];
    f[2] = x[(b*CIN + 2)*NPIX0 + p];
    f[3] = (float)i * (1.0f/255.0f);
    f[4] = (float)j * (1.0f/255.0f);
    float h[32];
    #pragma unroll
    for (int c1 = 0; c1 < 32; c1++) {
        float v = sb1[c1];
        #pragma unroll
        for (int q = 0; q < 5; q++) v = fmaf(sw1[c1*5+q], f[q], v);
        h[c1] = gelu_exact(v);
    }
    int base = b*NC*NP + i*HP + j;
    for (int c2 = 0; c2 < 64; c2++) {
        float v = sb2[c2];
        #pragma unroll
        for (int c1 = 0; c1 < 32; c1++) v = fmaf(sw2[c2*32+c1], h[c1], v);
        g_x[base + c2*NP] = v;
    }
}

// ---------------- fused local branch, f32x2, 256 threads --------------------
// stage A: 16 ty-groups x 8 rows = 128 rows in one pass; stage B: 4 rows each.
__global__ void __launch_bounds__(256, 2) k_local(
    const float* __restrict__ in, float* __restrict__ out,
    const float* __restrict__ WfT, const float* __restrict__ Bf,
    const float* __restrict__ W3T, const float* __restrict__ B3)
{
    extern __shared__ __align__(16) float sm_local[];
    float* sX = sm_local;           // 64x64
    float* sT = sm_local + 4096;    // 128x64
    float* sW = sm_local + 12288;   // 8192 floats
    const int tid = threadIdx.x;
    const int ty = tid >> 4, tx = tid & 15;   // 16 x 16
    const int x0 = tx * 4;
    const int base = blockIdx.y * (NC*NP) + blockIdx.x * 64;

    #pragma unroll
    for (int i = 0; i < 16; i++) {
        int idx = tid + i*256;
        sX[idx] = in[base + (idx >> 6)*NP + (idx & 63)];
    }
    #pragma unroll
    for (int i = 0; i < 32; i++) {
        int idx = tid + i*256;
        sW[idx] = WfT[idx];
    }
    __syncthreads();

    // ---- stage A: T = gelu(Wf X + bf)  (K=64), rows r0 = ty*8
    {
        const int r0 = ty * 8;
        u64 acc2[4][4];
        #pragma unroll
        for (int ip = 0; ip < 4; ip++) {
            u64 bp = pk(__ldg(&Bf[r0 + 2*ip]), __ldg(&Bf[r0 + 2*ip + 1]));
            #pragma unroll
            for (int j = 0; j < 4; j++) acc2[ip][j] = bp;
        }
        for (int k = 0; k < 64; k++) {
            const u64* wrow = (const u64*)(sW + k*128 + r0);
            u64 a0 = wrow[0], a1 = wrow[1], a2 = wrow[2], a3 = wrow[3];
            float4 b = *(const float4*)&sX[k*64 + x0];
            u64 b2v[4] = {pkdup(b.x), pkdup(b.y), pkdup(b.z), pkdup(b.w)};
            #pragma unroll
            for (int j = 0; j < 4; j++) {
                acc2[0][j] = f2fma(a0, b2v[j], acc2[0][j]);
                acc2[1][j] = f2fma(a1, b2v[j], acc2[1][j]);
                acc2[2][j] = f2fma(a2, b2v[j], acc2[2][j]);
                acc2[3][j] = f2fma(a3, b2v[j], acc2[3][j]);
            }
        }
        #pragma unroll
        for (int ip = 0; ip < 4; ip++) {
            float2 v0 = up(acc2[ip][0]), v1 = up(acc2[ip][1]);
            float2 v2 = up(acc2[ip][2]), v3 = up(acc2[ip][3]);
            *(float4*)&sT[(r0 + 2*ip    )*64 + x0] =
                make_float4(gelu_exact(v0.x), gelu_exact(v1.x), gelu_exact(v2.x), gelu_exact(v3.x));
            *(float4*)&sT[(r0 + 2*ip + 1)*64 + x0] =
                make_float4(gelu_exact(v0.y), gelu_exact(v1.y), gelu_exact(v2.y), gelu_exact(v3.y));
        }
    }
    __syncthreads();

    #pragma unroll
    for (int i = 0; i < 32; i++) {
        int idx = tid + i*256;
        sW[idx] = W3T[idx];
    }
    __syncthreads();

    // ---- stage B: OUT = W3 T + b3 (K=128), rows r0b = ty*4
    {
        const int r0b = ty * 4;
        u64 acc2[2][4];
        #pragma unroll
        for (int ip = 0; ip < 2; ip++) {
            u64 bp = pk(__ldg(&B3[r0b + 2*ip]), __ldg(&B3[r0b + 2*ip + 1]));
            #pragma unroll
            for (int j = 0; j < 4; j++) acc2[ip][j] = bp;
        }
        for (int k = 0; k < 128; k++) {
            const u64* wrow = (const u64*)(sW + k*64 + r0b);
            u64 a0 = wrow[0], a1 = wrow[1];
            float4 b = *(const float4*)&sT[k*64 + x0];
            u64 b2v[4] = {pkdup(b.x), pkdup(b.y), pkdup(b.z), pkdup(b.w)};
            #pragma unroll
            for (int j = 0; j < 4; j++) {
                acc2[0][j] = f2fma(a0, b2v[j], acc2[0][j]);
                acc2[1][j] = f2fma(a1, b2v[j], acc2[1][j]);
            }
        }
        #pragma unroll
        for (int ip = 0; ip < 2; ip++) {
            float2 v0 = up(acc2[ip][0]), v1 = up(acc2[ip][1]);
            float2 v2 = up(acc2[ip][2]), v3 = up(acc2[ip][3]);
            *(float4*)&out[base + (r0b + 2*ip    )*NP + x0] = make_float4(v0.x, v1.x, v2.x, v3.x);
            *(float4*)&out[base + (r0b + 2*ip + 1)*NP + x0] = make_float4(v0.y, v1.y, v2.y, v3.y);
        }
    }
}

// ---------------- S1: row DFT, 2 mode-groups per bc (unchanged) --------------
__global__ void __launch_bounds__(264) k_dft_rows() {
    extern __shared__ __align__(16) float2 fy_s[];   // 17 x 264
    const int bc = blockIdx.x, mgrp = blockIdx.y;
    const int m_base = mgrp * 16;
    const int tid = threadIdx.x;
    for (int idx = tid; idx < 17*HP; idx += 264) {
        int ml = idx / HP, y = idx % HP;
        int m = m_base + ml;
        float2 f;
        if (m < 32) f = g_Fy[m*HP + y];
        else { f = g_Fy[32*HP + y]; f.y = -f.y; }
        fy_s[idx] = f;
    }
    __syncthreads();
    const int xt = tid % 66, rq = tid / 66;
    const int x0 = xt * 4, ml0 = rq * 4;
    const bool five = (rq == 3);
    const float* img = g_x + bc*NP;
    u64 acc2[5][4];
    #pragma unroll
    for (int r = 0; r < 5; r++)
        #pragma unroll
        for (int j = 0; j < 4; j++) acc2[r][j] = 0ULL;

    float4 va = __ldg((const float4*)(img + HP + x0));
    float4 vb = __ldg((const float4*)(img + 263*HP + x0));
    for (int y = 1; y <= 131; y++) {
        float4 na = va, nb = vb;
        if (y < 131) {
            na = __ldg((const float4*)(img + (y+1)*HP + x0));
            nb = __ldg((const float4*)(img + (263-y)*HP + x0));
        }
        u64 pd[4] = { pk(va.x+vb.x, va.x-vb.x), pk(va.y+vb.y, va.y-vb.y),
                      pk(va.z+vb.z, va.z-vb.z), pk(va.w+vb.w, va.w-vb.w) };
        #pragma unroll
        for (int r = 0; r < 4; r++) {
            u64 f2 = *(const u64*)&fy_s[(ml0 + r)*HP + y];
            #pragma unroll
            for (int j = 0; j < 4; j++)
                acc2[r][j] = f2fma(pd[j], f2, acc2[r][j]);
        }
        if (five) {
            u64 f2 = *(const u64*)&fy_s[16*HP + y];
            #pragma unroll
            for (int j = 0; j < 4; j++)
                acc2[4][j] = f2fma(pd[j], f2, acc2[4][j]);
        }
        va = na; vb = nb;
    }
    {
        float4 v0   = __ldg((const float4*)(img + x0));
        float4 v132 = __ldg((const float4*)(img + 132*HP + x0));
        u64 z0[4] = {pk(v0.x,0.f),  pk(v0.y,0.f),  pk(v0.z,0.f),  pk(v0.w,0.f)};
        u64 z1[4] = {pk(v132.x,0.f),pk(v132.y,0.f),pk(v132.z,0.f),pk(v132.w,0.f)};
        #pragma unroll
        for (int r = 0; r < 4; r++) {
            u64 c132 = pkdup(fy_s[(ml0 + r)*HP + 132].x);
            #pragma unroll
            for (int j = 0; j < 4; j++)
                acc2[r][j] = f2fma(z1[j], c132, f2add(acc2[r][j], z0[j]));
        }
        if (five) {
            u64 c132 = pkdup(fy_s[16*HP + 132].x);
            #pragma unroll
            for (int j = 0; j < 4; j++)
                acc2[4][j] = f2fma(z1[j], c132, f2add(acc2[4][j], z0[j]));
        }
    }
    #pragma unroll
    for (int r = 0; r < 4; r++) {
        int m = m_base + ml0 + r;
        u64* dst = (u64*)&g_T1[(bc*33 + m)*HP + x0];
        #pragma unroll
        for (int j = 0; j < 4; j++) dst[j] = acc2[r][j];
    }
    if (five) {
        u64* dst = (u64*)&g_T1[(bc*33 + m_base + 16)*HP + x0];
        #pragma unroll
        for (int j = 0; j < 4; j++) dst[j] = acc2[4][j];
    }
}

// ---------------- S2: col DFT, 2 row-groups per bc (unchanged) ---------------
__global__ void __launch_bounds__(256) k_dft_cols() {
    extern __shared__ __align__(16) float2 t1s[];
    const int bc = blockIdx.x, by = blockIdx.y;
    const int tid = threadIdx.x;
    const int nrows = by ? 17 : 16;
    const int roff = by * 16 * HP;
    for (int idx = tid; idx < nrows*HP; idx += 256)
        t1s[idx] = g_T1[bc*(33*HP) + roff + idx];
    __syncthreads();
    const int k = tid & 31, rq = tid >> 5;
    u64 P1[2] = {0,0};
    u64 P2[2] = {0,0};
    u64 T1v = 0, T2v = 0;
    const bool do32 = (by == 1) && (rq == 0);
    for (int x = 0; x < HP; x++) {
        float2 f = __ldg(&g_FxT[x*NM + k]);
        u64 fx = pkdup(f.x), fy = pkdup(f.y);
        #pragma unroll
        for (int j = 0; j < 2; j++) {
            u64 pv = *(const u64*)&t1s[(rq + 8*j)*HP + x];
            P1[j] = f2fma(pv, fx, P1[j]);
            P2[j] = f2fma(pv, fy, P2[j]);
        }
        if (do32) {
            u64 pv = *(const u64*)&t1s[16*HP + x];
            T1v = f2fma(pv, fx, T1v);
            T2v = f2fma(pv, fy, T2v);
        }
    }
    #pragma unroll
    for (int j = 0; j < 2; j++) {
        int m = by*16 + rq + 8*j;
        float2 a = up(P1[j]);
        float2 b = up(P2[j]);
        g_xf[(bc*NR + m)*NM + k] = make_float2(a.x - b.y, b.x + a.y);
        if (m >= 1)
            g_xf[(bc*NR + (64 - m))*NM + k] = make_float2(a.x + b.y, b.x - a.y);
    }
    if (do32) {
        float2 a = up(T1v);
        float2 b = up(T2v);
        g_xf[(bc*NR + 32)*NM + k] = make_float2(a.x + b.y, b.x - a.y);
    }
}

// ---------------- S3: channel mix, f32x2 (ar,ai) accumulators ----------------
__global__ void __launch_bounds__(256) k_chanmix(
    const float* __restrict__ w1r, const float* __restrict__ w1i,
    const float* __restrict__ w2r, const float* __restrict__ w2i)
{
    extern __shared__ __align__(16) float2 xs[];
    const int r = blockIdx.y, oh = blockIdx.x;
    const float* wr; const float* wi; int m1;
    if (r < 32) { wr = w1r; wi = w1i; m1 = r; }
    else        { wr = w2r; wi = w2i; m1 = r - 32; }
    const int tid = threadIdx.x;
    for (int idx = tid; idx < NB*NC*NM; idx += 256) {
        int b = idx >> 11, i = (idx >> 5) & 63, kk = idx & 31;
        xs[idx] = g_xf[((b*NC + i)*NR + r)*NM + kk];
    }
    __syncthreads();
    const int k = tid & 31, og = tid >> 5;
    const int o0 = oh*16 + og*2;
    const int woff = m1*NM + k;
    u64 acc[2][4];
    #pragma unroll
    for (int oo = 0; oo < 2; oo++)
        #pragma unroll
        for (int b = 0; b < 4; b++) acc[oo][b] = 0ULL;
    #pragma unroll 2
    for (int i = 0; i < NC; i++) {
        float wre0 = __ldg(&wr[(i*64 + o0    )*1024 + woff]);
        float wim0 = __ldg(&wi[(i*64 + o0    )*1024 + woff]);
        float wre1 = __ldg(&wr[(i*64 + o0 + 1)*1024 + woff]);
        float wim1 = __ldg(&wi[(i*64 + o0 + 1)*1024 + woff]);
        u64 w0a = pk(wre0, wim0), w0b = pk(-wim0, wre0);
        u64 w1a = pk(wre1, wim1), w1b = pk(-wim1, wre1);
        #pragma unroll
        for (int b = 0; b < 4; b++) {
            float2 xv = xs[(b*NC + i)*NM + k];
            u64 xx = pkdup(xv.x), xy = pkdup(xv.y);
            acc[0][b] = f2fma(xx, w0a, f2fma(xy, w0b, acc[0][b]));
            acc[1][b] = f2fma(xx, w1a, f2fma(xy, w1b, acc[1][b]));
        }
    }
    #pragma unroll
    for (int oo = 0; oo < 2; oo++)
        #pragma unroll
        for (int b = 0; b < 4; b++)
            *(u64*)&g_of[((b*NC + o0 + oo)*NR + r)*NM + k] = acc[oo][b];
}

// ---------------- fused inverse: 4 y-chunks per bc (unchanged) ---------------
template<bool LAST>
__global__ void __launch_bounds__(272) k_inv(float* __restrict__ out) {
    extern __shared__ __align__(16) float2 sm_inv[];
    float2* os = sm_inv;
    float2* Us = sm_inv + 2048;
    const int bo = blockIdx.x, ch = blockIdx.y;
    const int ybase = ch*68 - ((ch >= 3) ? 4 : 0);
    const int ngrp  = (ch < 2) ? 17 : 16;
    const int tid = threadIdx.x;
    for (int idx = tid; idx < 2048; idx += 272)
        os[idx] = g_of[bo*2048 + idx];
    __syncthreads();
    for (int idx = tid; idx < 31*32; idx += 272) {
        int m = (idx >> 5) + 1, k = idx & 31;
        float2 A = os[m*NM + k], B = os[(64 - m)*NM + k];
        os[m*NM + k]        = make_float2(A.x + B.x, A.y - B.y);
        os[(64 - m)*NM + k] = make_float2(A.y + B.y, A.x - B.x);
    }
    __syncthreads();

    if (tid < 256) {
        const int k = tid & 31, yq = tid >> 5;
        const float2 o0  = os[k];
        const float2 o32 = os[32*NM + k];
        const u64 o0x = pkdup(o0.x), o0y = pkdup(o0.y);
        const u64 p32x = pkdup(o32.x), p32y = pkdup(o32.y), n32y = pkdup(-o32.y);
        for (int g = yq; g < ngrp; g += 8) {
            int y0 = ybase + g*4;
            ulonglong2 C32 = __ldg((const ulonglong2*)&g_Fyc[32*HP + y0]);
            ulonglong2 S32 = __ldg((const ulonglong2*)&g_Fys[32*HP + y0]);
            u64 R01 = f2fma(p32x, C32.x, f2fma(n32y, S32.x, o0x));
            u64 R23 = f2fma(p32x, C32.y, f2fma(n32y, S32.y, o0x));
            u64 I01 = f2fma(p32y, C32.x, f2fma(p32x, S32.x, o0y));
            u64 I23 = f2fma(p32y, C32.y, f2fma(p32x, S32.y, o0y));
            #pragma unroll 4
            for (int m = 1; m <= 31; m++) {
                float2 Ps = os[m*NM + k];
                float2 Qs = os[(64 - m)*NM + k];
                ulonglong2 C = __ldg((const ulonglong2*)&g_Fyc[m*HP + y0]);
                ulonglong2 S = __ldg((const ulonglong2*)&g_Fys[m*HP + y0]);
                u64 px_ = pkdup(Ps.x), py_ = pkdup(Ps.y);
                u64 qx_ = pkdup(Qs.x), qy_ = pkdup(-Qs.y);
                R01 = f2fma(px_, C.x, f2fma(py_, S.x, R01));
                R23 = f2fma(px_, C.y, f2fma(py_, S.y, R23));
                I01 = f2fma(qx_, C.x, f2fma(qy_, S.x, I01));
                I23 = f2fma(qx_, C.y, f2fma(qy_, S.y, I23));
            }
            float2 r01 = up(R01), r23 = up(R23), i01 = up(I01), i23 = up(I23);
            int yl = g*4;
            Us[(yl+0)*NM + k] = make_float2(r01.x*INV_HP, i01.x*INV_HP);
            Us[(yl+1)*NM + k] = make_float2(r01.y*INV_HP, i01.y*INV_HP);
            Us[(yl+2)*NM + k] = make_float2(r23.x*INV_HP, i23.x*INV_HP);
            Us[(yl+3)*NM + k] = make_float2(r23.y*INV_HP, i23.y*INV_HP);
        }
    }
    __syncthreads();

    const int xt = tid % 34, yq2 = tid / 34;
    const int x0 = xt * 4;
    for (int g = yq2; g < ngrp; g += 8) {
        int yl = g*4;
        u64 EO[4][4];
        float u0[4];
        #pragma unroll
        for (int j = 0; j < 4; j++) {
            u0[j] = Us[(yl + j)*NM].x;
            #pragma unroll
            for (int q = 0; q < 4; q++) EO[j][q] = 0ULL;
        }
        for (int k = 1; k < NM; k++) {
            const ulonglong2* fp = (const ulonglong2*)&g_Fx[k*HP + x0];
            ulonglong2 wA = __ldg(fp);
            ulonglong2 wB = __ldg(fp + 1);
            #pragma unroll
            for (int j = 0; j < 4; j++) {
                u64 u = *(const u64*)&Us[(yl + j)*NM + k];
                EO[j][0] = f2fma(u, wA.x, EO[j][0]);
                EO[j][1] = f2fma(u, wA.y, EO[j][1]);
                EO[j][2] = f2fma(u, wB.x, EO[j][2]);
                EO[j][3] = f2fma(u, wB.y, EO[j][3]);
            }
        }
        #pragma unroll
        for (int j = 0; j < 4; j++) {
            int y = ybase + yl + j;
            float2 eo[4] = {up(EO[j][0]), up(EO[j][1]), up(EO[j][2]), up(EO[j][3])};
            if (xt < 33) {
                int idx = bo*NP + y*HP + x0;
                float4 h = *(const float4*)&g_hbr[idx];
                float4 rv = make_float4(
                    h.x + (u0[j] + 2.f*(eo[0].x + eo[0].y))*INV_HP,
                    h.y + (u0[j] + 2.f*(eo[1].x + eo[1].y))*INV_HP,
                    h.z + (u0[j] + 2.f*(eo[2].x + eo[2].y))*INV_HP,
                    h.w + (u0[j] + 2.f*(eo[3].x + eo[3].y))*INV_HP);
                if (LAST) { if (y < H0) *(float4*)&out[bo*NPIX0 + y*W0 + x0] = rv; }
                else      *(float4*)&g_x[idx] = rv;
                #pragma unroll
                for (int q = 0; q < 4; q++) {
                    if (xt == 0 && q == 0) continue;
                    int xm = 264 - (x0 + q);
                    float hm = __ldg(&g_hbr[bo*NP + y*HP + xm]);
                    float vm = hm + (u0[j] + 2.f*(eo[q].x - eo[q].y))*INV_HP;
                    if (LAST) { if (y < H0 && xm < W0) out[bo*NPIX0 + y*W0 + xm] = vm; }
                    else      g_x[bo*NP + y*HP + xm] = vm;
                }
            } else {
                int idx = bo*NP + y*HP + 132;
                float hm = __ldg(&g_hbr[idx]);
                float vm = hm + (u0[j] + 2.f*(eo[0].x + eo[0].y))*INV_HP;
                if (LAST) { if (y < H0) out[bo*NPIX0 + y*W0 + 132] = vm; }
                else      g_x[idx] = vm;
            }
        }
    }
}

// ---------------- launch -----------------------------------------------------
extern "C" void kernel_launch(void* const* d_in, const int* in_sizes, int n_in,
                              void* d_out, int out_size)
{
    const float* x   = (const float*)d_in[0];
    const float* lw1 = (const float*)d_in[1];
    const float* lb1 = (const float*)d_in[2];
    const float* lw2 = (const float*)d_in[3];
    const float* lb2 = (const float*)d_in[4];
    const float* cw  = (const float*)d_in[5];
    const float* cb  = (const float*)d_in[6];
    const float* m1w = (const float*)d_in[7];
    const float* m1b = (const float*)d_in[8];
    const float* m2w = (const float*)d_in[9];
    const float* m2b = (const float*)d_in[10];
    const float* s1r = (const float*)d_in[11];
    const float* s1i = (const float*)d_in[12];
    const float* s2r = (const float*)d_in[13];
    const float* s2i = (const float*)d_in[14];
    float* out = (float*)d_out;

    float *px, *ph, *pwf, *pw3, *pbf;
    cudaGetSymbolAddress((void**)&px,  g_x);
    cudaGetSymbolAddress((void**)&ph,  g_hbr);
    cudaGetSymbolAddress((void**)&pwf, g_WfT);
    cudaGetSymbolAddress((void**)&pw3, g_W3T);
    cudaGetSymbolAddress((void**)&pbf, g_bf);

    const int LOCAL_SMEM = 20480 * 4;              // 81920 B
    const int DFTR_SMEM  = 17 * HP * 8;            // 35904 B
    const int DFTC_SMEM  = 17 * HP * 8;            // 35904 B
    const int CMIX_SMEM  = NB*NC*NM * 8;           // 65536 B
    const int INV_SMEM   = (2048 + 68*NM) * 8;     // 33792 B
    cudaFuncSetAttribute(k_local,      cudaFuncAttributeMaxDynamicSharedMemorySize, LOCAL_SMEM);
    cudaFuncSetAttribute(k_chanmix,    cudaFuncAttributeMaxDynamicSharedMemorySize, CMIX_SMEM);

    k_tables<<<132, 256>>>();
    k_wfuse<<<194, 256>>>(cw, cb, m1w, m1b, m2w);
    k_zero_pad<<<4160, 256>>>();
    k_lift<<<dim3(256, NB), 256>>>(x, lw1, lb1, lw2, lb2);

    for (int L = 0; L < 3; L++) {
        k_local<<<dim3(NP/64, NB), 256, LOCAL_SMEM>>>(
            px, ph, pwf + L*8192, pbf + L*128, pw3 + L*8192, m2b + L*64);
        k_dft_rows<<<dim3(NB*NC, 2), 264, DFTR_SMEM>>>();
        k_dft_cols<<<dim3(NB*NC, 2), 256, DFTC_SMEM>>>();
        k_chanmix<<<dim3(4, 64), 256, CMIX_SMEM>>>(s1r + L*SPW, s1i + L*SPW, s2r + L*SPW, s2i + L*SPW);
        if (L < 2) k_inv<false><<<dim3(NB*NC, 4), 272, INV_SMEM>>>(out);
        else       k_inv<true ><<<dim3(NB*NC, 4), 272, INV_SMEM>>>(out);
    }
}

// round 11
// speedup vs baseline: 1.0733x; 1.0733x over previous
#include <cuda_runtime.h>
#include <math.h>

#define NB 4
#define CIN 3
#define NC 64
#define H0 256
#define W0 256
#define NPIX0 (H0*W0)
#define HP 264
#define NP (HP*HP)      /* 69696 */
#define NR 64
#define NM 32
#define SPW (64*64*32*32)
#define INV_HP (1.0f/264.0f)

typedef unsigned long long u64;

// ---------------- f32x2 packed-FMA helpers -----------------------------------
__device__ __forceinline__ u64 pk(float lo, float hi) {
    u64 r; asm("mov.b64 %0, {%1, %2};" : "=l"(r) : "f"(lo), "f"(hi)); return r;
}
__device__ __forceinline__ u64 pkdup(float v) { return pk(v, v); }
__device__ __forceinline__ float2 up(u64 v) {
    float lo, hi; asm("mov.b64 {%0, %1}, %2;" : "=f"(lo), "=f"(hi) : "l"(v));
    return make_float2(lo, hi);
}
__device__ __forceinline__ u64 f2fma(u64 a, u64 b, u64 c) {
    u64 d; asm("fma.rn.f32x2 %0, %1, %2, %3;" : "=l"(d) : "l"(a), "l"(b), "l"(c)); return d;
}
__device__ __forceinline__ u64 f2add(u64 a, u64 b) {
    u64 d; asm("add.rn.f32x2 %0, %1, %2;" : "=l"(d) : "l"(a), "l"(b)); return d;
}

// ---------------- scratch ----------------------------------------------------
__device__ float  g_x  [NB*NC*NP];
__device__ float  g_hbr[NB*NC*NP];
__device__ float2 g_T1 [NB*NC*33*HP];
__device__ float2 g_xf [NB*NC*NR*NM];
__device__ float2 g_of [NB*NC*NR*NM];
__device__ float2 g_Fy [NR*HP];
__device__ float2 g_Fx [NM*HP];
__device__ float2 g_FxT[HP*NM];
__device__ float  g_Fyc[33*HP];
__device__ float  g_Fys[33*HP];
__device__ float  g_WfT[3*64*128];
__device__ float  g_W3T[3*128*64];
__device__ float  g_bf [3*128];

__device__ __forceinline__ float gelu_exact(float v) {
    return 0.5f * v * (1.0f + erff(v * 0.70710678118654752440f));
}

// ---------------- init --------------------------------------------------------
__global__ void k_tables() {
    int idx = blockIdx.x * 256 + threadIdx.x;
    if (idx < NR*HP) {
        int r = idx / HP, y = idx % HP;
        int ky = (r < 32) ? r : r + 200;
        int m = (ky * y) % HP;
        double a = 6.283185307179586 * (double)m / (double)HP;
        float2 f = make_float2((float)cos(a), (float)(-sin(a)));
        g_Fy[idx] = f;
        if (r <= 32) { g_Fyc[r*HP + y] = f.x; g_Fys[r*HP + y] = f.y; }
    } else if (idx < NR*HP + NM*HP) {
        int j = idx - NR*HP;
        int k = j / HP, xx = j % HP;
        int m = (k * xx) % HP;
        double a = 6.283185307179586 * (double)m / (double)HP;
        float2 f = make_float2((float)cos(a), (float)(-sin(a)));
        g_Fx[j] = f;
        g_FxT[xx*NM + k] = f;
    }
}

__global__ void k_wfuse(const float* __restrict__ cw,  const float* __restrict__ cb,
                        const float* __restrict__ m1w, const float* __restrict__ m1b,
                        const float* __restrict__ m2w) {
    int idx = blockIdx.x * 256 + threadIdx.x;
    if (idx < 3*8192) {
        int L = idx / 8192, r = idx % 8192, k = r >> 7, o = r & 127;
        const float* W2 = m1w + L*8192;
        const float* W1 = cw  + L*4096;
        double s = 0.0;
        for (int j = 0; j < 64; j++) s += (double)W2[o*64 + j] * (double)W1[j*64 + k];
        g_WfT[idx] = (float)s;
    } else if (idx < 6*8192) {
        int i = idx - 3*8192;
        int L = i / 8192, r = i % 8192, k = r >> 6, o = r & 63;
        g_W3T[i] = m2w[L*8192 + o*128 + k];
    } else if (idx < 6*8192 + 384) {
        int i = idx - 6*8192;
        int L = i / 128, o = i % 128;
        const float* W2 = m1w + L*8192;
        double s = (double)m1b[L*128 + o];
        for (int j = 0; j < 64; j++) s += (double)W2[o*64 + j] * (double)cb[L*64 + j];
        g_bf[i] = (float)s;
    }
}

// zero only the right/bottom padding bands
__global__ void k_zero_pad() {
    int idx = blockIdx.x * 256 + threadIdx.x;   // 256 images x 4160 px
    int img = idx / 4160, r = idx % 4160;
    int row, col;
    if (r < 2048) { row = r >> 3; col = 256 + (r & 7); }
    else          { int rr = r - 2048; row = 256 + rr / HP; col = rr % HP; }
    g_x[img*NP + row*HP + col] = 0.0f;
}

// ---------------- lift: 5 -> 32 (GELU) -> 64 (round-8 proven scalar) --------
__global__ void __launch_bounds__(256) k_lift(
    const float* __restrict__ x,
    const float* __restrict__ w1, const float* __restrict__ b1,
    const float* __restrict__ w2, const float* __restrict__ b2)
{
    __shared__ float sw1[32*5], sb1[32], sw2[64*32], sb2[64];
    for (int i = threadIdx.x; i < 160;  i += 256) sw1[i] = w1[i];
    for (int i = threadIdx.x; i < 32;   i += 256) sb1[i] = b1[i];
    for (int i = threadIdx.x; i < 2048; i += 256) sw2[i] = w2[i];
    for (int i = threadIdx.x; i < 64;   i += 256) sb2[i] = b2[i];
    __syncthreads();
    int b = blockIdx.y;
    int p = blockIdx.x * 256 + threadIdx.x;
    int i = p >> 8, j = p & 255;
    float f[5];
    f[0] = x[(b*CIN + 0)*NPIX0 + p];
    f[1] = x[(b*CIN + 1)*NPIX0 + p];
    f[2] = x[(b*CIN + 2)*NPIX0 + p];
    f[3] = (float)i * (1.0f/255.0f);
    f[4] = (float)j * (1.0f/255.0f);
    float h[32];
    #pragma unroll
    for (int c1 = 0; c1 < 32; c1++) {
        float v = sb1[c1];
        #pragma unroll
        for (int q = 0; q < 5; q++) v = fmaf(sw1[c1*5+q], f[q], v);
        h[c1] = gelu_exact(v);
    }
    int base = b*NC*NP + i*HP + j;
    for (int c2 = 0; c2 < 64; c2++) {
        float v = sb2[c2];
        #pragma unroll
        for (int c1 = 0; c1 < 32; c1++) v = fmaf(sw2[c2*32+c1], h[c1], v);
        g_x[base + c2*NP] = v;
    }
}

// ---------------- fused local branch, f32x2, 128 threads (round-8 proven) ---
__global__ void __launch_bounds__(128, 2) k_local(
    const float* __restrict__ in, float* __restrict__ out,
    const float* __restrict__ WfT, const float* __restrict__ Bf,
    const float* __restrict__ W3T, const float* __restrict__ B3)
{
    extern __shared__ __align__(16) float sm_local[];
    float* sX = sm_local;           // 64x64
    float* sT = sm_local + 4096;    // 128x64
    float* sW = sm_local + 12288;   // 8192 floats
    const int tid = threadIdx.x;
    const int ty = tid >> 4, tx = tid & 15;
    const int r0 = ty * 8, x0 = tx * 4;
    const int base = blockIdx.y * (NC*NP) + blockIdx.x * 64;

    #pragma unroll
    for (int i = 0; i < 32; i++) {
        int idx = tid + i*128;
        sX[idx] = in[base + (idx >> 6)*NP + (idx & 63)];
    }
    #pragma unroll
    for (int i = 0; i < 64; i++) {
        int idx = tid + i*128;
        sW[idx] = WfT[idx];
    }
    __syncthreads();

    #pragma unroll
    for (int h = 0; h < 2; h++) {
        u64 acc2[4][4];
        #pragma unroll
        for (int ip = 0; ip < 4; ip++) {
            u64 bp = pk(__ldg(&Bf[h*64 + r0 + 2*ip]), __ldg(&Bf[h*64 + r0 + 2*ip + 1]));
            #pragma unroll
            for (int j = 0; j < 4; j++) acc2[ip][j] = bp;
        }
        for (int k = 0; k < 64; k++) {
            const u64* wrow = (const u64*)(sW + k*128 + h*64 + r0);
            u64 a0 = wrow[0], a1 = wrow[1], a2 = wrow[2], a3 = wrow[3];
            float4 b = *(const float4*)&sX[k*64 + x0];
            u64 b2v[4] = {pkdup(b.x), pkdup(b.y), pkdup(b.z), pkdup(b.w)};
            #pragma unroll
            for (int j = 0; j < 4; j++) {
                acc2[0][j] = f2fma(a0, b2v[j], acc2[0][j]);
                acc2[1][j] = f2fma(a1, b2v[j], acc2[1][j]);
                acc2[2][j] = f2fma(a2, b2v[j], acc2[2][j]);
                acc2[3][j] = f2fma(a3, b2v[j], acc2[3][j]);
            }
        }
        #pragma unroll
        for (int ip = 0; ip < 4; ip++) {
            float2 v0 = up(acc2[ip][0]), v1 = up(acc2[ip][1]);
            float2 v2 = up(acc2[ip][2]), v3 = up(acc2[ip][3]);
            *(float4*)&sT[(h*64 + r0 + 2*ip    )*64 + x0] =
                make_float4(gelu_exact(v0.x), gelu_exact(v1.x), gelu_exact(v2.x), gelu_exact(v3.x));
            *(float4*)&sT[(h*64 + r0 + 2*ip + 1)*64 + x0] =
                make_float4(gelu_exact(v0.y), gelu_exact(v1.y), gelu_exact(v2.y), gelu_exact(v3.y));
        }
    }
    __syncthreads();

    #pragma unroll
    for (int i = 0; i < 64; i++) {
        int idx = tid + i*128;
        sW[idx] = W3T[idx];
    }
    __syncthreads();

    {
        u64 acc2[4][4];
        #pragma unroll
        for (int ip = 0; ip < 4; ip++) {
            u64 bp = pk(__ldg(&B3[r0 + 2*ip]), __ldg(&B3[r0 + 2*ip + 1]));
            #pragma unroll
            for (int j = 0; j < 4; j++) acc2[ip][j] = bp;
        }
        for (int k = 0; k < 128; k++) {
            const u64* wrow = (const u64*)(sW + k*64 + r0);
            u64 a0 = wrow[0], a1 = wrow[1], a2 = wrow[2], a3 = wrow[3];
            float4 b = *(const float4*)&sT[k*64 + x0];
            u64 b2v[4] = {pkdup(b.x), pkdup(b.y), pkdup(b.z), pkdup(b.w)};
            #pragma unroll
            for (int j = 0; j < 4; j++) {
                acc2[0][j] = f2fma(a0, b2v[j], acc2[0][j]);
                acc2[1][j] = f2fma(a1, b2v[j], acc2[1][j]);
                acc2[2][j] = f2fma(a2, b2v[j], acc2[2][j]);
                acc2[3][j] = f2fma(a3, b2v[j], acc2[3][j]);
            }
        }
        #pragma unroll
        for (int ip = 0; ip < 4; ip++) {
            float2 v0 = up(acc2[ip][0]), v1 = up(acc2[ip][1]);
            float2 v2 = up(acc2[ip][2]), v3 = up(acc2[ip][3]);
            *(float4*)&out[base + (r0 + 2*ip    )*NP + x0] = make_float4(v0.x, v1.x, v2.x, v3.x);
            *(float4*)&out[base + (r0 + 2*ip + 1)*NP + x0] = make_float4(v0.y, v1.y, v2.y, v3.y);
        }
    }
}

// ---------------- S1: row DFT, 2 mode-groups per bc --------------------------
__global__ void __launch_bounds__(264) k_dft_rows() {
    extern __shared__ __align__(16) float2 fy_s[];   // 17 x 264
    const int bc = blockIdx.x, mgrp = blockIdx.y;
    const int m_base = mgrp * 16;
    const int tid = threadIdx.x;
    for (int idx = tid; idx < 17*HP; idx += 264) {
        int ml = idx / HP, y = idx % HP;
        int m = m_base + ml;
        float2 f;
        if (m < 32) f = g_Fy[m*HP + y];
        else { f = g_Fy[32*HP + y]; f.y = -f.y; }
        fy_s[idx] = f;
    }
    __syncthreads();
    const int xt = tid % 66, rq = tid / 66;
    const int x0 = xt * 4, ml0 = rq * 4;
    const bool five = (rq == 3);
    const float* img = g_x + bc*NP;
    u64 acc2[5][4];
    #pragma unroll
    for (int r = 0; r < 5; r++)
        #pragma unroll
        for (int j = 0; j < 4; j++) acc2[r][j] = 0ULL;

    float4 va = __ldg((const float4*)(img + HP + x0));
    float4 vb = __ldg((const float4*)(img + 263*HP + x0));
    for (int y = 1; y <= 131; y++) {
        float4 na = va, nb = vb;
        if (y < 131) {
            na = __ldg((const float4*)(img + (y+1)*HP + x0));
            nb = __ldg((const float4*)(img + (263-y)*HP + x0));
        }
        u64 pd[4] = { pk(va.x+vb.x, va.x-vb.x), pk(va.y+vb.y, va.y-vb.y),
                      pk(va.z+vb.z, va.z-vb.z), pk(va.w+vb.w, va.w-vb.w) };
        #pragma unroll
        for (int r = 0; r < 4; r++) {
            u64 f2 = *(const u64*)&fy_s[(ml0 + r)*HP + y];
            #pragma unroll
            for (int j = 0; j < 4; j++)
                acc2[r][j] = f2fma(pd[j], f2, acc2[r][j]);
        }
        if (five) {
            u64 f2 = *(const u64*)&fy_s[16*HP + y];
            #pragma unroll
            for (int j = 0; j < 4; j++)
                acc2[4][j] = f2fma(pd[j], f2, acc2[4][j]);
        }
        va = na; vb = nb;
    }
    {
        float4 v0   = __ldg((const float4*)(img + x0));
        float4 v132 = __ldg((const float4*)(img + 132*HP + x0));
        u64 z0[4] = {pk(v0.x,0.f),  pk(v0.y,0.f),  pk(v0.z,0.f),  pk(v0.w,0.f)};
        u64 z1[4] = {pk(v132.x,0.f),pk(v132.y,0.f),pk(v132.z,0.f),pk(v132.w,0.f)};
        #pragma unroll
        for (int r = 0; r < 4; r++) {
            u64 c132 = pkdup(fy_s[(ml0 + r)*HP + 132].x);
            #pragma unroll
            for (int j = 0; j < 4; j++)
                acc2[r][j] = f2fma(z1[j], c132, f2add(acc2[r][j], z0[j]));
        }
        if (five) {
            u64 c132 = pkdup(fy_s[16*HP + 132].x);
            #pragma unroll
            for (int j = 0; j < 4; j++)
                acc2[4][j] = f2fma(z1[j], c132, f2add(acc2[4][j], z0[j]));
        }
    }
    #pragma unroll
    for (int r = 0; r < 4; r++) {
        int m = m_base + ml0 + r;
        u64* dst = (u64*)&g_T1[(bc*33 + m)*HP + x0];
        #pragma unroll
        for (int j = 0; j < 4; j++) dst[j] = acc2[r][j];
    }
    if (five) {
        u64* dst = (u64*)&g_T1[(bc*33 + m_base + 16)*HP + x0];
        #pragma unroll
        for (int j = 0; j < 4; j++) dst[j] = acc2[4][j];
    }
}

// ---------------- S2: col DFT, 2 row-groups per bc ---------------------------
__global__ void __launch_bounds__(256) k_dft_cols() {
    extern __shared__ __align__(16) float2 t1s[];
    const int bc = blockIdx.x, by = blockIdx.y;
    const int tid = threadIdx.x;
    const int nrows = by ? 17 : 16;
    const int roff = by * 16 * HP;
    for (int idx = tid; idx < nrows*HP; idx += 256)
        t1s[idx] = g_T1[bc*(33*HP) + roff + idx];
    __syncthreads();
    const int k = tid & 31, rq = tid >> 5;
    u64 P1[2] = {0,0};
    u64 P2[2] = {0,0};
    u64 T1v = 0, T2v = 0;
    const bool do32 = (by == 1) && (rq == 0);
    for (int x = 0; x < HP; x++) {
        float2 f = __ldg(&g_FxT[x*NM + k]);
        u64 fx = pkdup(f.x), fy = pkdup(f.y);
        #pragma unroll
        for (int j = 0; j < 2; j++) {
            u64 pv = *(const u64*)&t1s[(rq + 8*j)*HP + x];
            P1[j] = f2fma(pv, fx, P1[j]);
            P2[j] = f2fma(pv, fy, P2[j]);
        }
        if (do32) {
            u64 pv = *(const u64*)&t1s[16*HP + x];
            T1v = f2fma(pv, fx, T1v);
            T2v = f2fma(pv, fy, T2v);
        }
    }
    #pragma unroll
    for (int j = 0; j < 2; j++) {
        int m = by*16 + rq + 8*j;
        float2 a = up(P1[j]);
        float2 b = up(P2[j]);
        g_xf[(bc*NR + m)*NM + k] = make_float2(a.x - b.y, b.x + a.y);
        if (m >= 1)
            g_xf[(bc*NR + (64 - m))*NM + k] = make_float2(a.x + b.y, b.x - a.y);
    }
    if (do32) {
        float2 a = up(T1v);
        float2 b = up(T2v);
        g_xf[(bc*NR + 32)*NM + k] = make_float2(a.x + b.y, b.x - a.y);
    }
}

// ---------------- S3: channel mix, f32x2 (ar,ai) accumulators ----------------
__global__ void __launch_bounds__(256) k_chanmix(
    const float* __restrict__ w1r, const float* __restrict__ w1i,
    const float* __restrict__ w2r, const float* __restrict__ w2i)
{
    extern __shared__ __align__(16) float2 xs[];
    const int r = blockIdx.y, oh = blockIdx.x;
    const float* wr; const float* wi; int m1;
    if (r < 32) { wr = w1r; wi = w1i; m1 = r; }
    else        { wr = w2r; wi = w2i; m1 = r - 32; }
    const int tid = threadIdx.x;
    for (int idx = tid; idx < NB*NC*NM; idx += 256) {
        int b = idx >> 11, i = (idx >> 5) & 63, kk = idx & 31;
        xs[idx] = g_xf[((b*NC + i)*NR + r)*NM + kk];
    }
    __syncthreads();
    const int k = tid & 31, og = tid >> 5;
    const int o0 = oh*16 + og*2;
    const int woff = m1*NM + k;
    u64 acc[2][4];
    #pragma unroll
    for (int oo = 0; oo < 2; oo++)
        #pragma unroll
        for (int b = 0; b < 4; b++) acc[oo][b] = 0ULL;
    #pragma unroll 2
    for (int i = 0; i < NC; i++) {
        float wre0 = __ldg(&wr[(i*64 + o0    )*1024 + woff]);
        float wim0 = __ldg(&wi[(i*64 + o0    )*1024 + woff]);
        float wre1 = __ldg(&wr[(i*64 + o0 + 1)*1024 + woff]);
        float wim1 = __ldg(&wi[(i*64 + o0 + 1)*1024 + woff]);
        u64 w0a = pk(wre0, wim0), w0b = pk(-wim0, wre0);
        u64 w1a = pk(wre1, wim1), w1b = pk(-wim1, wre1);
        #pragma unroll
        for (int b = 0; b < 4; b++) {
            float2 xv = xs[(b*NC + i)*NM + k];
            u64 xx = pkdup(xv.x), xy = pkdup(xv.y);
            acc[0][b] = f2fma(xx, w0a, f2fma(xy, w0b, acc[0][b]));
            acc[1][b] = f2fma(xx, w1a, f2fma(xy, w1b, acc[1][b]));
        }
    }
    #pragma unroll
    for (int oo = 0; oo < 2; oo++)
        #pragma unroll
        for (int b = 0; b < 4; b++)
            *(u64*)&g_of[((b*NC + o0 + oo)*NR + r)*NM + k] = acc[oo][b];
}

// ---------------- fused inverse: 4 y-chunks per bc ---------------------------
template<bool LAST>
__global__ void __launch_bounds__(272) k_inv(float* __restrict__ out) {
    extern __shared__ __align__(16) float2 sm_inv[];
    float2* os = sm_inv;
    float2* Us = sm_inv + 2048;
    const int bo = blockIdx.x, ch = blockIdx.y;
    const int ybase = ch*68 - ((ch >= 3) ? 4 : 0);
    const int ngrp  = (ch < 2) ? 17 : 16;
    const int tid = threadIdx.x;
    for (int idx = tid; idx < 2048; idx += 272)
        os[idx] = g_of[bo*2048 + idx];
    __syncthreads();
    for (int idx = tid; idx < 31*32; idx += 272) {
        int m = (idx >> 5) + 1, k = idx & 31;
        float2 A = os[m*NM + k], B = os[(64 - m)*NM + k];
        os[m*NM + k]        = make_float2(A.x + B.x, A.y - B.y);
        os[(64 - m)*NM + k] = make_float2(A.y + B.y, A.x - B.x);
    }
    __syncthreads();

    if (tid < 256) {
        const int k = tid & 31, yq = tid >> 5;
        const float2 o0  = os[k];
        const float2 o32 = os[32*NM + k];
        const u64 o0x = pkdup(o0.x), o0y = pkdup(o0.y);
        const u64 p32x = pkdup(o32.x), p32y = pkdup(o32.y), n32y = pkdup(-o32.y);
        for (int g = yq; g < ngrp; g += 8) {
            int y0 = ybase + g*4;
            ulonglong2 C32 = __ldg((const ulonglong2*)&g_Fyc[32*HP + y0]);
            ulonglong2 S32 = __ldg((const ulonglong2*)&g_Fys[32*HP + y0]);
            u64 R01 = f2fma(p32x, C32.x, f2fma(n32y, S32.x, o0x));
            u64 R23 = f2fma(p32x, C32.y, f2fma(n32y, S32.y, o0x));
            u64 I01 = f2fma(p32y, C32.x, f2fma(p32x, S32.x, o0y));
            u64 I23 = f2fma(p32y, C32.y, f2fma(p32x, S32.y, o0y));
            #pragma unroll 4
            for (int m = 1; m <= 31; m++) {
                float2 Ps = os[m*NM + k];
                float2 Qs = os[(64 - m)*NM + k];
                ulonglong2 C = __ldg((const ulonglong2*)&g_Fyc[m*HP + y0]);
                ulonglong2 S = __ldg((const ulonglong2*)&g_Fys[m*HP + y0]);
                u64 px_ = pkdup(Ps.x), py_ = pkdup(Ps.y);
                u64 qx_ = pkdup(Qs.x), qy_ = pkdup(-Qs.y);
                R01 = f2fma(px_, C.x, f2fma(py_, S.x, R01));
                R23 = f2fma(px_, C.y, f2fma(py_, S.y, R23));
                I01 = f2fma(qx_, C.x, f2fma(qy_, S.x, I01));
                I23 = f2fma(qx_, C.y, f2fma(qy_, S.y, I23));
            }
            float2 r01 = up(R01), r23 = up(R23), i01 = up(I01), i23 = up(I23);
            int yl = g*4;
            Us[(yl+0)*NM + k] = make_float2(r01.x*INV_HP, i01.x*INV_HP);
            Us[(yl+1)*NM + k] = make_float2(r01.y*INV_HP, i01.y*INV_HP);
            Us[(yl+2)*NM + k] = make_float2(r23.x*INV_HP, i23.x*INV_HP);
            Us[(yl+3)*NM + k] = make_float2(r23.y*INV_HP, i23.y*INV_HP);
        }
    }
    __syncthreads();

    const int xt = tid % 34, yq2 = tid / 34;
    const int x0 = xt * 4;
    for (int g = yq2; g < ngrp; g += 8) {
        int yl = g*4;
        u64 EO[4][4];
        float u0[4];
        #pragma unroll
        for (int j = 0; j < 4; j++) {
            u0[j] = Us[(yl + j)*NM].x;
            #pragma unroll
            for (int q = 0; q < 4; q++) EO[j][q] = 0ULL;
        }
        for (int k = 1; k < NM; k++) {
            const ulonglong2* fp = (const ulonglong2*)&g_Fx[k*HP + x0];
            ulonglong2 wA = __ldg(fp);
            ulonglong2 wB = __ldg(fp + 1);
            #pragma unroll
            for (int j = 0; j < 4; j++) {
                u64 u = *(const u64*)&Us[(yl + j)*NM + k];
                EO[j][0] = f2fma(u, wA.x, EO[j][0]);
                EO[j][1] = f2fma(u, wA.y, EO[j][1]);
                EO[j][2] = f2fma(u, wB.x, EO[j][2]);
                EO[j][3] = f2fma(u, wB.y, EO[j][3]);
            }
        }
        #pragma unroll
        for (int j = 0; j < 4; j++) {
            int y = ybase + yl + j;
            float2 eo[4] = {up(EO[j][0]), up(EO[j][1]), up(EO[j][2]), up(EO[j][3])};
            if (xt < 33) {
                int idx = bo*NP + y*HP + x0;
                float4 h = *(const float4*)&g_hbr[idx];
                float4 rv = make_float4(
                    h.x + (u0[j] + 2.f*(eo[0].x + eo[0].y))*INV_HP,
                    h.y + (u0[j] + 2.f*(eo[1].x + eo[1].y))*INV_HP,
                    h.z + (u0[j] + 2.f*(eo[2].x + eo[2].y))*INV_HP,
                    h.w + (u0[j] + 2.f*(eo[3].x + eo[3].y))*INV_HP);
                if (LAST) { if (y < H0) *(float4*)&out[bo*NPIX0 + y*W0 + x0] = rv; }
                else      *(float4*)&g_x[idx] = rv;
                #pragma unroll
                for (int q = 0; q < 4; q++) {
                    if (xt == 0 && q == 0) continue;
                    int xm = 264 - (x0 + q);
                    float hm = __ldg(&g_hbr[bo*NP + y*HP + xm]);
                    float vm = hm + (u0[j] + 2.f*(eo[q].x - eo[q].y))*INV_HP;
                    if (LAST) { if (y < H0 && xm < W0) out[bo*NPIX0 + y*W0 + xm] = vm; }
                    else      g_x[bo*NP + y*HP + xm] = vm;
                }
            } else {
                int idx = bo*NP + y*HP + 132;
                float hm = __ldg(&g_hbr[idx]);
                float vm = hm + (u0[j] + 2.f*(eo[0].x + eo[0].y))*INV_HP;
                if (LAST) { if (y < H0) out[bo*NPIX0 + y*W0 + 132] = vm; }
                else      g_x[idx] = vm;
            }
        }
    }
}

// ---------------- launch -----------------------------------------------------
extern "C" void kernel_launch(void* const* d_in, const int* in_sizes, int n_in,
                              void* d_out, int out_size)
{
    const float* x   = (const float*)d_in[0];
    const float* lw1 = (const float*)d_in[1];
    const float* lb1 = (const float*)d_in[2];
    const float* lw2 = (const float*)d_in[3];
    const float* lb2 = (const float*)d_in[4];
    const float* cw  = (const float*)d_in[5];
    const float* cb  = (const float*)d_in[6];
    const float* m1w = (const float*)d_in[7];
    const float* m1b = (const float*)d_in[8];
    const float* m2w = (const float*)d_in[9];
    const float* m2b = (const float*)d_in[10];
    const float* s1r = (const float*)d_in[11];
    const float* s1i = (const float*)d_in[12];
    const float* s2r = (const float*)d_in[13];
    const float* s2i = (const float*)d_in[14];
    float* out = (float*)d_out;

    float *px, *ph, *pwf, *pw3, *pbf;
    cudaGetSymbolAddress((void**)&px,  g_x);
    cudaGetSymbolAddress((void**)&ph,  g_hbr);
    cudaGetSymbolAddress((void**)&pwf, g_WfT);
    cudaGetSymbolAddress((void**)&pw3, g_W3T);
    cudaGetSymbolAddress((void**)&pbf, g_bf);

    const int LOCAL_SMEM = 20480 * 4;              // 81920 B
    const int DFTR_SMEM  = 17 * HP * 8;            // 35904 B
    const int DFTC_SMEM  = 17 * HP * 8;            // 35904 B
    const int CMIX_SMEM  = NB*NC*NM * 8;           // 65536 B
    const int INV_SMEM   = (2048 + 68*NM) * 8;     // 33792 B
    cudaFuncSetAttribute(k_local,      cudaFuncAttributeMaxDynamicSharedMemorySize, LOCAL_SMEM);
    cudaFuncSetAttribute(k_chanmix,    cudaFuncAttributeMaxDynamicSharedMemorySize, CMIX_SMEM);

    k_tables<<<132, 256>>>();
    k_wfuse<<<194, 256>>>(cw, cb, m1w, m1b, m2w);
    k_zero_pad<<<4160, 256>>>();
    k_lift<<<dim3(256, NB), 256>>>(x, lw1, lb1, lw2, lb2);

    for (int L = 0; L < 3; L++) {
        k_local<<<dim3(NP/64, NB), 128, LOCAL_SMEM>>>(
            px, ph, pwf + L*8192, pbf + L*128, pw3 + L*8192, m2b + L*64);
        k_dft_rows<<<dim3(NB*NC, 2), 264, DFTR_SMEM>>>();
        k_dft_cols<<<dim3(NB*NC, 2), 256, DFTC_SMEM>>>();
        k_chanmix<<<dim3(4, 64), 256, CMIX_SMEM>>>(s1r + L*SPW, s1i + L*SPW, s2r + L*SPW, s2i + L*SPW);
        if (L < 2) k_inv<false><<<dim3(NB*NC, 4), 272, INV_SMEM>>>(out);
        else       k_inv<true ><<<dim3(NB*NC, 4), 272, INV_SMEM>>>(out);
    }
}

// round 12
// speedup vs baseline: 1.1083x; 1.0326x over previous
#include <cuda_runtime.h>
#include <math.h>

#define NB 4
#define CIN 3
#define NC 64
#define H0 256
#define W0 256
#define NPIX0 (H0*W0)
#define HP 264
#define NP (HP*HP)      /* 69696 */
#define NR 64
#define NM 32
#define SPW (64*64*32*32)
#define INV_HP (1.0f/264.0f)

typedef unsigned long long u64;

// ---------------- f32x2 packed-FMA helpers -----------------------------------
__device__ __forceinline__ u64 pk(float lo, float hi) {
    u64 r; asm("mov.b64 %0, {%1, %2};" : "=l"(r) : "f"(lo), "f"(hi)); return r;
}
__device__ __forceinline__ u64 pkdup(float v) { return pk(v, v); }
__device__ __forceinline__ float2 up(u64 v) {
    float lo, hi; asm("mov.b64 {%0, %1}, %2;" : "=f"(lo), "=f"(hi) : "l"(v));
    return make_float2(lo, hi);
}
__device__ __forceinline__ u64 f2fma(u64 a, u64 b, u64 c) {
    u64 d; asm("fma.rn.f32x2 %0, %1, %2, %3;" : "=l"(d) : "l"(a), "l"(b), "l"(c)); return d;
}
__device__ __forceinline__ u64 f2add(u64 a, u64 b) {
    u64 d; asm("add.rn.f32x2 %0, %1, %2;" : "=l"(d) : "l"(a), "l"(b)); return d;
}

// ---------------- scratch ----------------------------------------------------
__device__ float  g_x  [NB*NC*NP];
__device__ float  g_hbr[NB*NC*NP];
__device__ float2 g_T1 [NB*NC*33*HP];
__device__ float2 g_xf [NB*NC*NR*NM];
__device__ float2 g_of [NB*NC*NR*NM];
__device__ float2 g_Fy [NR*HP];
__device__ float2 g_Fx [NM*HP];
__device__ float2 g_FxT[HP*NM];
__device__ float  g_Fyc[33*HP];
__device__ float  g_Fys[33*HP];
__device__ float  g_WfT[3*64*128];
__device__ float  g_W3T[3*128*64];
__device__ float  g_bf [3*128];

__device__ __forceinline__ float gelu_exact(float v) {
    return 0.5f * v * (1.0f + erff(v * 0.70710678118654752440f));
}

// ---------------- init --------------------------------------------------------
__global__ void k_tables() {
    int idx = blockIdx.x * 256 + threadIdx.x;
    if (idx < NR*HP) {
        int r = idx / HP, y = idx % HP;
        int ky = (r < 32) ? r : r + 200;
        int m = (ky * y) % HP;
        double a = 6.283185307179586 * (double)m / (double)HP;
        float2 f = make_float2((float)cos(a), (float)(-sin(a)));
        g_Fy[idx] = f;
        if (r <= 32) { g_Fyc[r*HP + y] = f.x; g_Fys[r*HP + y] = f.y; }
    } else if (idx < NR*HP + NM*HP) {
        int j = idx - NR*HP;
        int k = j / HP, xx = j % HP;
        int m = (k * xx) % HP;
        double a = 6.283185307179586 * (double)m / (double)HP;
        float2 f = make_float2((float)cos(a), (float)(-sin(a)));
        g_Fx[j] = f;
        g_FxT[xx*NM + k] = f;
    }
}

__global__ void k_wfuse(const float* __restrict__ cw,  const float* __restrict__ cb,
                        const float* __restrict__ m1w, const float* __restrict__ m1b,
                        const float* __restrict__ m2w) {
    int idx = blockIdx.x * 256 + threadIdx.x;
    if (idx < 3*8192) {
        int L = idx / 8192, r = idx % 8192, k = r >> 7, o = r & 127;
        const float* W2 = m1w + L*8192;
        const float* W1 = cw  + L*4096;
        double s = 0.0;
        for (int j = 0; j < 64; j++) s += (double)W2[o*64 + j] * (double)W1[j*64 + k];
        g_WfT[idx] = (float)s;
    } else if (idx < 6*8192) {
        int i = idx - 3*8192;
        int L = i / 8192, r = i % 8192, k = r >> 6, o = r & 63;
        g_W3T[i] = m2w[L*8192 + o*128 + k];
    } else if (idx < 6*8192 + 384) {
        int i = idx - 6*8192;
        int L = i / 128, o = i % 128;
        const float* W2 = m1w + L*8192;
        double s = (double)m1b[L*128 + o];
        for (int j = 0; j < 64; j++) s += (double)W2[o*64 + j] * (double)cb[L*64 + j];
        g_bf[i] = (float)s;
    }
}

// zero only the right/bottom padding bands
__global__ void k_zero_pad() {
    int idx = blockIdx.x * 256 + threadIdx.x;   // 256 images x 4160 px
    int img = idx / 4160, r = idx % 4160;
    int row, col;
    if (r < 2048) { row = r >> 3; col = 256 + (r & 7); }
    else          { int rr = r - 2048; row = 256 + rr / HP; col = rr % HP; }
    g_x[img*NP + row*HP + col] = 0.0f;
}

// ---------------- lift: 5 -> 32 (GELU) -> 64 --------------------------------
__global__ void __launch_bounds__(256) k_lift(
    const float* __restrict__ x,
    const float* __restrict__ w1, const float* __restrict__ b1,
    const float* __restrict__ w2, const float* __restrict__ b2)
{
    __shared__ float sw1[32*5], sb1[32], sw2[64*32], sb2[64];
    for (int i = threadIdx.x; i < 160;  i += 256) sw1[i] = w1[i];
    for (int i = threadIdx.x; i < 32;   i += 256) sb1[i] = b1[i];
    for (int i = threadIdx.x; i < 2048; i += 256) sw2[i] = w2[i];
    for (int i = threadIdx.x; i < 64;   i += 256) sb2[i] = b2[i];
    __syncthreads();
    int b = blockIdx.y;
    int p = blockIdx.x * 256 + threadIdx.x;
    int i = p >> 8, j = p & 255;
    float f[5];
    f[0] = x[(b*CIN + 0)*NPIX0 + p];
    f[1] = x[(b*CIN + 1)*NPIX0 + p];
    f[2] = x[(b*CIN + 2)*NPIX0 + p];
    f[3] = (float)i * (1.0f/255.0f);
    f[4] = (float)j * (1.0f/255.0f);
    float h[32];
    #pragma unroll
    for (int c1 = 0; c1 < 32; c1++) {
        float v = sb1[c1];
        #pragma unroll
        for (int q = 0; q < 5; q++) v = fmaf(sw1[c1*5+q], f[q], v);
        h[c1] = gelu_exact(v);
    }
    int base = b*NC*NP + i*HP + j;
    for (int c2 = 0; c2 < 64; c2++) {
        float v = sb2[c2];
        #pragma unroll
        for (int c1 = 0; c1 < 32; c1++) v = fmaf(sw2[c2*32+c1], h[c1], v);
        g_x[base + c2*NP] = v;
    }
}

// ---------------- fused local branch, f32x2, 128 threads --------------------
__global__ void __launch_bounds__(128, 2) k_local(
    const float* __restrict__ in, float* __restrict__ out,
    const float* __restrict__ WfT, const float* __restrict__ Bf,
    const float* __restrict__ W3T, const float* __restrict__ B3)
{
    extern __shared__ __align__(16) float sm_local[];
    float* sX = sm_local;           // 64x64
    float* sT = sm_local + 4096;    // 128x64
    float* sW = sm_local + 12288;   // 8192 floats
    const int tid = threadIdx.x;
    const int ty = tid >> 4, tx = tid & 15;
    const int r0 = ty * 8, x0 = tx * 4;
    const int base = blockIdx.y * (NC*NP) + blockIdx.x * 64;

    #pragma unroll
    for (int i = 0; i < 32; i++) {
        int idx = tid + i*128;
        sX[idx] = in[base + (idx >> 6)*NP + (idx & 63)];
    }
    #pragma unroll
    for (int i = 0; i < 64; i++) {
        int idx = tid + i*128;
        sW[idx] = WfT[idx];
    }
    __syncthreads();

    #pragma unroll
    for (int h = 0; h < 2; h++) {
        u64 acc2[4][4];
        #pragma unroll
        for (int ip = 0; ip < 4; ip++) {
            u64 bp = pk(__ldg(&Bf[h*64 + r0 + 2*ip]), __ldg(&Bf[h*64 + r0 + 2*ip + 1]));
            #pragma unroll
            for (int j = 0; j < 4; j++) acc2[ip][j] = bp;
        }
        for (int k = 0; k < 64; k++) {
            const u64* wrow = (const u64*)(sW + k*128 + h*64 + r0);
            u64 a0 = wrow[0], a1 = wrow[1], a2 = wrow[2], a3 = wrow[3];
            float4 b = *(const float4*)&sX[k*64 + x0];
            u64 b2v[4] = {pkdup(b.x), pkdup(b.y), pkdup(b.z), pkdup(b.w)};
            #pragma unroll
            for (int j = 0; j < 4; j++) {
                acc2[0][j] = f2fma(a0, b2v[j], acc2[0][j]);
                acc2[1][j] = f2fma(a1, b2v[j], acc2[1][j]);
                acc2[2][j] = f2fma(a2, b2v[j], acc2[2][j]);
                acc2[3][j] = f2fma(a3, b2v[j], acc2[3][j]);
            }
        }
        #pragma unroll
        for (int ip = 0; ip < 4; ip++) {
            float2 v0 = up(acc2[ip][0]), v1 = up(acc2[ip][1]);
            float2 v2 = up(acc2[ip][2]), v3 = up(acc2[ip][3]);
            *(float4*)&sT[(h*64 + r0 + 2*ip    )*64 + x0] =
                make_float4(gelu_exact(v0.x), gelu_exact(v1.x), gelu_exact(v2.x), gelu_exact(v3.x));
            *(float4*)&sT[(h*64 + r0 + 2*ip + 1)*64 + x0] =
                make_float4(gelu_exact(v0.y), gelu_exact(v1.y), gelu_exact(v2.y), gelu_exact(v3.y));
        }
    }
    __syncthreads();

    #pragma unroll
    for (int i = 0; i < 64; i++) {
        int idx = tid + i*128;
        sW[idx] = W3T[idx];
    }
    __syncthreads();

    {
        u64 acc2[4][4];
        #pragma unroll
        for (int ip = 0; ip < 4; ip++) {
            u64 bp = pk(__ldg(&B3[r0 + 2*ip]), __ldg(&B3[r0 + 2*ip + 1]));
            #pragma unroll
            for (int j = 0; j < 4; j++) acc2[ip][j] = bp;
        }
        for (int k = 0; k < 128; k++) {
            const u64* wrow = (const u64*)(sW + k*64 + r0);
            u64 a0 = wrow[0], a1 = wrow[1], a2 = wrow[2], a3 = wrow[3];
            float4 b = *(const float4*)&sT[k*64 + x0];
            u64 b2v[4] = {pkdup(b.x), pkdup(b.y), pkdup(b.z), pkdup(b.w)};
            #pragma unroll
            for (int j = 0; j < 4; j++) {
                acc2[0][j] = f2fma(a0, b2v[j], acc2[0][j]);
                acc2[1][j] = f2fma(a1, b2v[j], acc2[1][j]);
                acc2[2][j] = f2fma(a2, b2v[j], acc2[2][j]);
                acc2[3][j] = f2fma(a3, b2v[j], acc2[3][j]);
            }
        }
        #pragma unroll
        for (int ip = 0; ip < 4; ip++) {
            float2 v0 = up(acc2[ip][0]), v1 = up(acc2[ip][1]);
            float2 v2 = up(acc2[ip][2]), v3 = up(acc2[ip][3]);
            *(float4*)&out[base + (r0 + 2*ip    )*NP + x0] = make_float4(v0.x, v1.x, v2.x, v3.x);
            *(float4*)&out[base + (r0 + 2*ip + 1)*NP + x0] = make_float4(v0.y, v1.y, v2.y, v3.y);
        }
    }
}

// ---------------- S1: row DFT, 2 mode-groups per bc --------------------------
__global__ void __launch_bounds__(264) k_dft_rows() {
    extern __shared__ __align__(16) float2 fy_s[];   // 17 x 264
    const int bc = blockIdx.x, mgrp = blockIdx.y;
    const int m_base = mgrp * 16;
    const int tid = threadIdx.x;
    for (int idx = tid; idx < 17*HP; idx += 264) {
        int ml = idx / HP, y = idx % HP;
        int m = m_base + ml;
        float2 f;
        if (m < 32) f = g_Fy[m*HP + y];
        else { f = g_Fy[32*HP + y]; f.y = -f.y; }
        fy_s[idx] = f;
    }
    __syncthreads();
    const int xt = tid % 66, rq = tid / 66;
    const int x0 = xt * 4, ml0 = rq * 4;
    const bool five = (rq == 3);
    const float* img = g_x + bc*NP;
    u64 acc2[5][4];
    #pragma unroll
    for (int r = 0; r < 5; r++)
        #pragma unroll
        for (int j = 0; j < 4; j++) acc2[r][j] = 0ULL;

    float4 va = __ldg((const float4*)(img + HP + x0));
    float4 vb = __ldg((const float4*)(img + 263*HP + x0));
    for (int y = 1; y <= 131; y++) {
        float4 na = va, nb = vb;
        if (y < 131) {
            na = __ldg((const float4*)(img + (y+1)*HP + x0));
            nb = __ldg((const float4*)(img + (263-y)*HP + x0));
        }
        u64 pd[4] = { pk(va.x+vb.x, va.x-vb.x), pk(va.y+vb.y, va.y-vb.y),
                      pk(va.z+vb.z, va.z-vb.z), pk(va.w+vb.w, va.w-vb.w) };
        #pragma unroll
        for (int r = 0; r < 4; r++) {
            u64 f2 = *(const u64*)&fy_s[(ml0 + r)*HP + y];
            #pragma unroll
            for (int j = 0; j < 4; j++)
                acc2[r][j] = f2fma(pd[j], f2, acc2[r][j]);
        }
        if (five) {
            u64 f2 = *(const u64*)&fy_s[16*HP + y];
            #pragma unroll
            for (int j = 0; j < 4; j++)
                acc2[4][j] = f2fma(pd[j], f2, acc2[4][j]);
        }
        va = na; vb = nb;
    }
    {
        float4 v0   = __ldg((const float4*)(img + x0));
        float4 v132 = __ldg((const float4*)(img + 132*HP + x0));
        u64 z0[4] = {pk(v0.x,0.f),  pk(v0.y,0.f),  pk(v0.z,0.f),  pk(v0.w,0.f)};
        u64 z1[4] = {pk(v132.x,0.f),pk(v132.y,0.f),pk(v132.z,0.f),pk(v132.w,0.f)};
        #pragma unroll
        for (int r = 0; r < 4; r++) {
            u64 c132 = pkdup(fy_s[(ml0 + r)*HP + 132].x);
            #pragma unroll
            for (int j = 0; j < 4; j++)
                acc2[r][j] = f2fma(z1[j], c132, f2add(acc2[r][j], z0[j]));
        }
        if (five) {
            u64 c132 = pkdup(fy_s[16*HP + 132].x);
            #pragma unroll
            for (int j = 0; j < 4; j++)
                acc2[4][j] = f2fma(z1[j], c132, f2add(acc2[4][j], z0[j]));
        }
    }
    #pragma unroll
    for (int r = 0; r < 4; r++) {
        int m = m_base + ml0 + r;
        u64* dst = (u64*)&g_T1[(bc*33 + m)*HP + x0];
        #pragma unroll
        for (int j = 0; j < 4; j++) dst[j] = acc2[r][j];
    }
    if (five) {
        u64* dst = (u64*)&g_T1[(bc*33 + m_base + 16)*HP + x0];
        #pragma unroll
        for (int j = 0; j < 4; j++) dst[j] = acc2[4][j];
    }
}

// ---------------- S2: col DFT, 2 row-groups per bc ---------------------------
__global__ void __launch_bounds__(256) k_dft_cols() {
    extern __shared__ __align__(16) float2 t1s[];
    const int bc = blockIdx.x, by = blockIdx.y;
    const int tid = threadIdx.x;
    const int nrows = by ? 17 : 16;
    const int roff = by * 16 * HP;
    for (int idx = tid; idx < nrows*HP; idx += 256)
        t1s[idx] = g_T1[bc*(33*HP) + roff + idx];
    __syncthreads();
    const int k = tid & 31, rq = tid >> 5;
    u64 P1[2] = {0,0};
    u64 P2[2] = {0,0};
    u64 T1v = 0, T2v = 0;
    const bool do32 = (by == 1) && (rq == 0);
    for (int x = 0; x < HP; x++) {
        float2 f = __ldg(&g_FxT[x*NM + k]);
        u64 fx = pkdup(f.x), fy = pkdup(f.y);
        #pragma unroll
        for (int j = 0; j < 2; j++) {
            u64 pv = *(const u64*)&t1s[(rq + 8*j)*HP + x];
            P1[j] = f2fma(pv, fx, P1[j]);
            P2[j] = f2fma(pv, fy, P2[j]);
        }
        if (do32) {
            u64 pv = *(const u64*)&t1s[16*HP + x];
            T1v = f2fma(pv, fx, T1v);
            T2v = f2fma(pv, fy, T2v);
        }
    }
    #pragma unroll
    for (int j = 0; j < 2; j++) {
        int m = by*16 + rq + 8*j;
        float2 a = up(P1[j]);
        float2 b = up(P2[j]);
        g_xf[(bc*NR + m)*NM + k] = make_float2(a.x - b.y, b.x + a.y);
        if (m >= 1)
            g_xf[(bc*NR + (64 - m))*NM + k] = make_float2(a.x + b.y, b.x - a.y);
    }
    if (do32) {
        float2 a = up(T1v);
        float2 b = up(T2v);
        g_xf[(bc*NR + 32)*NM + k] = make_float2(a.x + b.y, b.x - a.y);
    }
}

// ---------------- S3: channel mix, f32x2 (ar,ai) accumulators ----------------
__global__ void __launch_bounds__(256) k_chanmix(
    const float* __restrict__ w1r, const float* __restrict__ w1i,
    const float* __restrict__ w2r, const float* __restrict__ w2i)
{
    extern __shared__ __align__(16) float2 xs[];
    const int r = blockIdx.y, oh = blockIdx.x;
    const float* wr; const float* wi; int m1;
    if (r < 32) { wr = w1r; wi = w1i; m1 = r; }
    else        { wr = w2r; wi = w2i; m1 = r - 32; }
    const int tid = threadIdx.x;
    for (int idx = tid; idx < NB*NC*NM; idx += 256) {
        int b = idx >> 11, i = (idx >> 5) & 63, kk = idx & 31;
        xs[idx] = g_xf[((b*NC + i)*NR + r)*NM + kk];
    }
    __syncthreads();
    const int k = tid & 31, og = tid >> 5;
    const int o0 = oh*16 + og*2;
    const int woff = m1*NM + k;
    u64 acc[2][4];
    #pragma unroll
    for (int oo = 0; oo < 2; oo++)
        #pragma unroll
        for (int b = 0; b < 4; b++) acc[oo][b] = 0ULL;
    #pragma unroll 2
    for (int i = 0; i < NC; i++) {
        float wre0 = __ldg(&wr[(i*64 + o0    )*1024 + woff]);
        float wim0 = __ldg(&wi[(i*64 + o0    )*1024 + woff]);
        float wre1 = __ldg(&wr[(i*64 + o0 + 1)*1024 + woff]);
        float wim1 = __ldg(&wi[(i*64 + o0 + 1)*1024 + woff]);
        u64 w0a = pk(wre0, wim0), w0b = pk(-wim0, wre0);
        u64 w1a = pk(wre1, wim1), w1b = pk(-wim1, wre1);
        #pragma unroll
        for (int b = 0; b < 4; b++) {
            float2 xv = xs[(b*NC + i)*NM + k];
            u64 xx = pkdup(xv.x), xy = pkdup(xv.y);
            acc[0][b] = f2fma(xx, w0a, f2fma(xy, w0b, acc[0][b]));
            acc[1][b] = f2fma(xx, w1a, f2fma(xy, w1b, acc[1][b]));
        }
    }
    #pragma unroll
    for (int oo = 0; oo < 2; oo++)
        #pragma unroll
        for (int b = 0; b < 4; b++)
            *(u64*)&g_of[((b*NC + o0 + oo)*NR + r)*NM + k] = acc[oo][b];
}

// ---------------- fused inverse: 4 y-chunks per bc ---------------------------
template<bool LAST>
__global__ void __launch_bounds__(272) k_inv(float* __restrict__ out) {
    extern __shared__ __align__(16) float2 sm_inv[];
    float2* os = sm_inv;
    float2* Us = sm_inv + 2048;
    const int bo = blockIdx.x, ch = blockIdx.y;
    const int ybase = ch*68 - ((ch >= 3) ? 4 : 0);
    const int ngrp  = (ch < 2) ? 17 : 16;
    const int tid = threadIdx.x;
    for (int idx = tid; idx < 2048; idx += 272)
        os[idx] = g_of[bo*2048 + idx];
    __syncthreads();
    for (int idx = tid; idx < 31*32; idx += 272) {
        int m = (idx >> 5) + 1, k = idx & 31;
        float2 A = os[m*NM + k], B = os[(64 - m)*NM + k];
        os[m*NM + k]        = make_float2(A.x + B.x, A.y - B.y);
        os[(64 - m)*NM + k] = make_float2(A.y + B.y, A.x - B.x);
    }
    __syncthreads();

    if (tid < 256) {
        const int k = tid & 31, yq = tid >> 5;
        const float2 o0  = os[k];
        const float2 o32 = os[32*NM + k];
        const u64 o0x = pkdup(o0.x), o0y = pkdup(o0.y);
        const u64 p32x = pkdup(o32.x), p32y = pkdup(o32.y), n32y = pkdup(-o32.y);
        for (int g = yq; g < ngrp; g += 8) {
            int y0 = ybase + g*4;
            ulonglong2 C32 = __ldg((const ulonglong2*)&g_Fyc[32*HP + y0]);
            ulonglong2 S32 = __ldg((const ulonglong2*)&g_Fys[32*HP + y0]);
            u64 R01 = f2fma(p32x, C32.x, f2fma(n32y, S32.x, o0x));
            u64 R23 = f2fma(p32x, C32.y, f2fma(n32y, S32.y, o0x));
            u64 I01 = f2fma(p32y, C32.x, f2fma(p32x, S32.x, o0y));
            u64 I23 = f2fma(p32y, C32.y, f2fma(p32x, S32.y, o0y));
            #pragma unroll 4
            for (int m = 1; m <= 31; m++) {
                float2 Ps = os[m*NM + k];
                float2 Qs = os[(64 - m)*NM + k];
                ulonglong2 C = __ldg((const ulonglong2*)&g_Fyc[m*HP + y0]);
                ulonglong2 S = __ldg((const ulonglong2*)&g_Fys[m*HP + y0]);
                u64 px_ = pkdup(Ps.x), py_ = pkdup(Ps.y);
                u64 qx_ = pkdup(Qs.x), qy_ = pkdup(-Qs.y);
                R01 = f2fma(px_, C.x, f2fma(py_, S.x, R01));
                R23 = f2fma(px_, C.y, f2fma(py_, S.y, R23));
                I01 = f2fma(qx_, C.x, f2fma(qy_, S.x, I01));
                I23 = f2fma(qx_, C.y, f2fma(qy_, S.y, I23));
            }
            float2 r01 = up(R01), r23 = up(R23), i01 = up(I01), i23 = up(I23);
            int yl = g*4;
            Us[(yl+0)*NM + k] = make_float2(r01.x*INV_HP, i01.x*INV_HP);
            Us[(yl+1)*NM + k] = make_float2(r01.y*INV_HP, i01.y*INV_HP);
            Us[(yl+2)*NM + k] = make_float2(r23.x*INV_HP, i23.x*INV_HP);
            Us[(yl+3)*NM + k] = make_float2(r23.y*INV_HP, i23.y*INV_HP);
        }
    }
    __syncthreads();

    const int xt = tid % 34, yq2 = tid / 34;
    const int x0 = xt * 4;
    for (int g = yq2; g < ngrp; g += 8) {
        int yl = g*4;
        u64 EO[4][4];
        float u0[4];
        #pragma unroll
        for (int j = 0; j < 4; j++) {
            u0[j] = Us[(yl + j)*NM].x;
            #pragma unroll
            for (int q = 0; q < 4; q++) EO[j][q] = 0ULL;
        }
        for (int k = 1; k < NM; k++) {
            const ulonglong2* fp = (const ulonglong2*)&g_Fx[k*HP + x0];
            ulonglong2 wA = __ldg(fp);
            ulonglong2 wB = __ldg(fp + 1);
            #pragma unroll
            for (int j = 0; j < 4; j++) {
                u64 u = *(const u64*)&Us[(yl + j)*NM + k];
                EO[j][0] = f2fma(u, wA.x, EO[j][0]);
                EO[j][1] = f2fma(u, wA.y, EO[j][1]);
                EO[j][2] = f2fma(u, wB.x, EO[j][2]);
                EO[j][3] = f2fma(u, wB.y, EO[j][3]);
            }
        }
        #pragma unroll
        for (int j = 0; j < 4; j++) {
            int y = ybase + yl + j;
            float2 eo[4] = {up(EO[j][0]), up(EO[j][1]), up(EO[j][2]), up(EO[j][3])};
            if (xt < 33) {
                int idx = bo*NP + y*HP + x0;
                float4 h = *(const float4*)&g_hbr[idx];
                float4 rv = make_float4(
                    h.x + (u0[j] + 2.f*(eo[0].x + eo[0].y))*INV_HP,
                    h.y + (u0[j] + 2.f*(eo[1].x + eo[1].y))*INV_HP,
                    h.z + (u0[j] + 2.f*(eo[2].x + eo[2].y))*INV_HP,
                    h.w + (u0[j] + 2.f*(eo[3].x + eo[3].y))*INV_HP);
                if (LAST) { if (y < H0) *(float4*)&out[bo*NPIX0 + y*W0 + x0] = rv; }
                else      *(float4*)&g_x[idx] = rv;
                #pragma unroll
                for (int q = 0; q < 4; q++) {
                    if (xt == 0 && q == 0) continue;
                    int xm = 264 - (x0 + q);
                    float hm = __ldg(&g_hbr[bo*NP + y*HP + xm]);
                    float vm = hm + (u0[j] + 2.f*(eo[q].x - eo[q].y))*INV_HP;
                    if (LAST) { if (y < H0 && xm < W0) out[bo*NPIX0 + y*W0 + xm] = vm; }
                    else      g_x[bo*NP + y*HP + xm] = vm;
                }
            } else {
                int idx = bo*NP + y*HP + 132;
                float hm = __ldg(&g_hbr[idx]);
                float vm = hm + (u0[j] + 2.f*(eo[0].x + eo[0].y))*INV_HP;
                if (LAST) { if (y < H0) out[bo*NPIX0 + y*W0 + 132] = vm; }
                else      g_x[idx] = vm;
            }
        }
    }
}

// ---------------- launch: two-stream overlap of local & spectral chains ------
extern "C" void kernel_launch(void* const* d_in, const int* in_sizes, int n_in,
                              void* d_out, int out_size)
{
    const float* x   = (const float*)d_in[0];
    const float* lw1 = (const float*)d_in[1];
    const float* lb1 = (const float*)d_in[2];
    const float* lw2 = (const float*)d_in[3];
    const float* lb2 = (const float*)d_in[4];
    const float* cw  = (const float*)d_in[5];
    const float* cb  = (const float*)d_in[6];
    const float* m1w = (const float*)d_in[7];
    const float* m1b = (const float*)d_in[8];
    const float* m2w = (const float*)d_in[9];
    const float* m2b = (const float*)d_in[10];
    const float* s1r = (const float*)d_in[11];
    const float* s1i = (const float*)d_in[12];
    const float* s2r = (const float*)d_in[13];
    const float* s2i = (const float*)d_in[14];
    float* out = (float*)d_out;

    float *px, *ph, *pwf, *pw3, *pbf;
    cudaGetSymbolAddress((void**)&px,  g_x);
    cudaGetSymbolAddress((void**)&ph,  g_hbr);
    cudaGetSymbolAddress((void**)&pwf, g_WfT);
    cudaGetSymbolAddress((void**)&pw3, g_W3T);
    cudaGetSymbolAddress((void**)&pbf, g_bf);

    const int LOCAL_SMEM = 20480 * 4;              // 81920 B
    const int DFTR_SMEM  = 17 * HP * 8;            // 35904 B
    const int DFTC_SMEM  = 17 * HP * 8;            // 35904 B
    const int CMIX_SMEM  = NB*NC*NM * 8;           // 65536 B
    const int INV_SMEM   = (2048 + 68*NM) * 8;     // 33792 B
    cudaFuncSetAttribute(k_local,      cudaFuncAttributeMaxDynamicSharedMemorySize, LOCAL_SMEM);
    cudaFuncSetAttribute(k_chanmix,    cudaFuncAttributeMaxDynamicSharedMemorySize, CMIX_SMEM);

    // one-time stream/event setup (first call = correctness pass, not captured)
    static cudaStream_t sp = nullptr;             // spectral side stream
    static cudaEvent_t evWf, evX[3], evSpec[3], evInit;
    if (!sp) {
        cudaStreamCreateWithFlags(&sp, cudaStreamNonBlocking);
        cudaEventCreateWithFlags(&evWf,   cudaEventDisableTiming);
        cudaEventCreateWithFlags(&evInit, cudaEventDisableTiming);
        for (int i = 0; i < 3; i++) {
            cudaEventCreateWithFlags(&evX[i],    cudaEventDisableTiming);
            cudaEventCreateWithFlags(&evSpec[i], cudaEventDisableTiming);
        }
    }

    // prologue: wfuse on sp, concurrent with tables/zero/lift on default
    cudaEventRecord(evInit, 0);
    cudaStreamWaitEvent(sp, evInit, 0);
    k_wfuse<<<194, 256, 0, sp>>>(cw, cb, m1w, m1b, m2w);
    cudaEventRecord(evWf, sp);

    k_tables<<<132, 256>>>();
    k_zero_pad<<<4160, 256>>>();
    k_lift<<<dim3(256, NB), 256>>>(x, lw1, lb1, lw2, lb2);
    cudaStreamWaitEvent(0, evWf, 0);              // Wf ready before first k_local

    for (int L = 0; L < 3; L++) {
        // g_x is ready on default stream here (lift or previous k_inv)
        cudaEventRecord(evX[L], 0);
        cudaStreamWaitEvent(sp, evX[L], 0);

        // spectral chain on sp
        k_dft_rows<<<dim3(NB*NC, 2), 264, DFTR_SMEM, sp>>>();
        k_dft_cols<<<dim3(NB*NC, 2), 256, DFTC_SMEM, sp>>>();
        k_chanmix<<<dim3(4, 64), 256, CMIX_SMEM, sp>>>(
            s1r + L*SPW, s1i + L*SPW, s2r + L*SPW, s2i + L*SPW);
        cudaEventRecord(evSpec[L], sp);

        // local branch on default stream (concurrent with spectral)
        k_local<<<dim3(NP/64, NB), 128, LOCAL_SMEM>>>(
            px, ph, pwf + L*8192, pbf + L*128, pw3 + L*8192, m2b + L*64);

        // join, then inverse (needs g_hbr + g_of)
        cudaStreamWaitEvent(0, evSpec[L], 0);
        if (L < 2) k_inv<false><<<dim3(NB*NC, 4), 272, INV_SMEM>>>(out);
        else       k_inv<true ><<<dim3(NB*NC, 4), 272, INV_SMEM>>>(out);
    }
}

// round 13
// speedup vs baseline: 1.1322x; 1.0215x over previous
#include <cuda_runtime.h>
#include <math.h>

#define NB 4
#define CIN 3
#define NC 64
#define H0 256
#define W0 256
#define NPIX0 (H0*W0)
#define HP 264
#define NP (HP*HP)      /* 69696 */
#define NR 64
#define NM 32
#define SPW (64*64*32*32)
#define INV_HP (1.0f/264.0f)

typedef unsigned long long u64;

// ---------------- f32x2 packed-FMA helpers -----------------------------------
__device__ __forceinline__ u64 pk(float lo, float hi) {
    u64 r; asm("mov.b64 %0, {%1, %2};" : "=l"(r) : "f"(lo), "f"(hi)); return r;
}
__device__ __forceinline__ u64 pkdup(float v) { return pk(v, v); }
__device__ __forceinline__ float2 up(u64 v) {
    float lo, hi; asm("mov.b64 {%0, %1}, %2;" : "=f"(lo), "=f"(hi) : "l"(v));
    return make_float2(lo, hi);
}
__device__ __forceinline__ u64 f2fma(u64 a, u64 b, u64 c) {
    u64 d; asm("fma.rn.f32x2 %0, %1, %2, %3;" : "=l"(d) : "l"(a), "l"(b), "l"(c)); return d;
}
__device__ __forceinline__ u64 f2add(u64 a, u64 b) {
    u64 d; asm("add.rn.f32x2 %0, %1, %2;" : "=l"(d) : "l"(a), "l"(b)); return d;
}

// ---------------- scratch ----------------------------------------------------
__device__ float  g_x  [NB*NC*NP];
__device__ float  g_hbr[NB*NC*NP];
__device__ float  g_sp [NB*NC*NP];     // spectral-branch inverse output
__device__ float2 g_T1 [NB*NC*33*HP];
__device__ float2 g_xf [NB*NC*NR*NM];
__device__ float2 g_of [NB*NC*NR*NM];
__device__ float2 g_Fy [NR*HP];
__device__ float2 g_Fx [NM*HP];
__device__ float2 g_FxT[HP*NM];
__device__ float  g_Fyc[33*HP];
__device__ float  g_Fys[33*HP];
__device__ float  g_WfT[3*64*128];
__device__ float  g_W3T[3*128*64];
__device__ float  g_bf [3*128];

__device__ __forceinline__ float gelu_exact(float v) {
    return 0.5f * v * (1.0f + erff(v * 0.70710678118654752440f));
}

// ---------------- init --------------------------------------------------------
__global__ void k_tables() {
    int idx = blockIdx.x * 256 + threadIdx.x;
    if (idx < NR*HP) {
        int r = idx / HP, y = idx % HP;
        int ky = (r < 32) ? r : r + 200;
        int m = (ky * y) % HP;
        double a = 6.283185307179586 * (double)m / (double)HP;
        float2 f = make_float2((float)cos(a), (float)(-sin(a)));
        g_Fy[idx] = f;
        if (r <= 32) { g_Fyc[r*HP + y] = f.x; g_Fys[r*HP + y] = f.y; }
    } else if (idx < NR*HP + NM*HP) {
        int j = idx - NR*HP;
        int k = j / HP, xx = j % HP;
        int m = (k * xx) % HP;
        double a = 6.283185307179586 * (double)m / (double)HP;
        float2 f = make_float2((float)cos(a), (float)(-sin(a)));
        g_Fx[j] = f;
        g_FxT[xx*NM + k] = f;
    }
}

__global__ void k_wfuse(const float* __restrict__ cw,  const float* __restrict__ cb,
                        const float* __restrict__ m1w, const float* __restrict__ m1b,
                        const float* __restrict__ m2w) {
    int idx = blockIdx.x * 256 + threadIdx.x;
    if (idx < 3*8192) {
        int L = idx / 8192, r = idx % 8192, k = r >> 7, o = r & 127;
        const float* W2 = m1w + L*8192;
        const float* W1 = cw  + L*4096;
        double s = 0.0;
        for (int j = 0; j < 64; j++) s += (double)W2[o*64 + j] * (double)W1[j*64 + k];
        g_WfT[idx] = (float)s;
    } else if (idx < 6*8192) {
        int i = idx - 3*8192;
        int L = i / 8192, r = i % 8192, k = r >> 6, o = r & 63;
        g_W3T[i] = m2w[L*8192 + o*128 + k];
    } else if (idx < 6*8192 + 384) {
        int i = idx - 6*8192;
        int L = i / 128, o = i % 128;
        const float* W2 = m1w + L*8192;
        double s = (double)m1b[L*128 + o];
        for (int j = 0; j < 64; j++) s += (double)W2[o*64 + j] * (double)cb[L*64 + j];
        g_bf[i] = (float)s;
    }
}

// zero only the right/bottom padding bands
__global__ void k_zero_pad() {
    int idx = blockIdx.x * 256 + threadIdx.x;   // 256 images x 4160 px
    int img = idx / 4160, r = idx % 4160;
    int row, col;
    if (r < 2048) { row = r >> 3; col = 256 + (r & 7); }
    else          { int rr = r - 2048; row = 256 + rr / HP; col = rr % HP; }
    g_x[img*NP + row*HP + col] = 0.0f;
}

// ---------------- lift: 5 -> 32 (GELU) -> 64 --------------------------------
__global__ void __launch_bounds__(256) k_lift(
    const float* __restrict__ x,
    const float* __restrict__ w1, const float* __restrict__ b1,
    const float* __restrict__ w2, const float* __restrict__ b2)
{
    __shared__ float sw1[32*5], sb1[32], sw2[64*32], sb2[64];
    for (int i = threadIdx.x; i < 160;  i += 256) sw1[i] = w1[i];
    for (int i = threadIdx.x; i < 32;   i += 256) sb1[i] = b1[i];
    for (int i = threadIdx.x; i < 2048; i += 256) sw2[i] = w2[i];
    for (int i = threadIdx.x; i < 64;   i += 256) sb2[i] = b2[i];
    __syncthreads();
    int b = blockIdx.y;
    int p = blockIdx.x * 256 + threadIdx.x;
    int i = p >> 8, j = p & 255;
    float f[5];
    f[0] = x[(b*CIN + 0)*NPIX0 + p];
    f[1] = x[(b*CIN + 1)*NPIX0 + p];
    f[2] = x[(b*CIN + 2)*NPIX0 + p];
    f[3] = (float)i * (1.0f/255.0f);
    f[4] = (float)j * (1.0f/255.0f);
    float h[32];
    #pragma unroll
    for (int c1 = 0; c1 < 32; c1++) {
        float v = sb1[c1];
        #pragma unroll
        for (int q = 0; q < 5; q++) v = fmaf(sw1[c1*5+q], f[q], v);
        h[c1] = gelu_exact(v);
    }
    int base = b*NC*NP + i*HP + j;
    for (int c2 = 0; c2 < 64; c2++) {
        float v = sb2[c2];
        #pragma unroll
        for (int c1 = 0; c1 < 32; c1++) v = fmaf(sw2[c2*32+c1], h[c1], v);
        g_x[base + c2*NP] = v;
    }
}

// ---------------- fused local branch, f32x2, 128 threads --------------------
__global__ void __launch_bounds__(128, 2) k_local(
    const float* __restrict__ in, float* __restrict__ out,
    const float* __restrict__ WfT, const float* __restrict__ Bf,
    const float* __restrict__ W3T, const float* __restrict__ B3)
{
    extern __shared__ __align__(16) float sm_local[];
    float* sX = sm_local;           // 64x64
    float* sT = sm_local + 4096;    // 128x64
    float* sW = sm_local + 12288;   // 8192 floats
    const int tid = threadIdx.x;
    const int ty = tid >> 4, tx = tid & 15;
    const int r0 = ty * 8, x0 = tx * 4;
    const int base = blockIdx.y * (NC*NP) + blockIdx.x * 64;

    #pragma unroll
    for (int i = 0; i < 32; i++) {
        int idx = tid + i*128;
        sX[idx] = in[base + (idx >> 6)*NP + (idx & 63)];
    }
    #pragma unroll
    for (int i = 0; i < 64; i++) {
        int idx = tid + i*128;
        sW[idx] = WfT[idx];
    }
    __syncthreads();

    #pragma unroll
    for (int h = 0; h < 2; h++) {
        u64 acc2[4][4];
        #pragma unroll
        for (int ip = 0; ip < 4; ip++) {
            u64 bp = pk(__ldg(&Bf[h*64 + r0 + 2*ip]), __ldg(&Bf[h*64 + r0 + 2*ip + 1]));
            #pragma unroll
            for (int j = 0; j < 4; j++) acc2[ip][j] = bp;
        }
        for (int k = 0; k < 64; k++) {
            const u64* wrow = (const u64*)(sW + k*128 + h*64 + r0);
            u64 a0 = wrow[0], a1 = wrow[1], a2 = wrow[2], a3 = wrow[3];
            float4 b = *(const float4*)&sX[k*64 + x0];
            u64 b2v[4] = {pkdup(b.x), pkdup(b.y), pkdup(b.z), pkdup(b.w)};
            #pragma unroll
            for (int j = 0; j < 4; j++) {
                acc2[0][j] = f2fma(a0, b2v[j], acc2[0][j]);
                acc2[1][j] = f2fma(a1, b2v[j], acc2[1][j]);
                acc2[2][j] = f2fma(a2, b2v[j], acc2[2][j]);
                acc2[3][j] = f2fma(a3, b2v[j], acc2[3][j]);
            }
        }
        #pragma unroll
        for (int ip = 0; ip < 4; ip++) {
            float2 v0 = up(acc2[ip][0]), v1 = up(acc2[ip][1]);
            float2 v2 = up(acc2[ip][2]), v3 = up(acc2[ip][3]);
            *(float4*)&sT[(h*64 + r0 + 2*ip    )*64 + x0] =
                make_float4(gelu_exact(v0.x), gelu_exact(v1.x), gelu_exact(v2.x), gelu_exact(v3.x));
            *(float4*)&sT[(h*64 + r0 + 2*ip + 1)*64 + x0] =
                make_float4(gelu_exact(v0.y), gelu_exact(v1.y), gelu_exact(v2.y), gelu_exact(v3.y));
        }
    }
    __syncthreads();

    #pragma unroll
    for (int i = 0; i < 64; i++) {
        int idx = tid + i*128;
        sW[idx] = W3T[idx];
    }
    __syncthreads();

    {
        u64 acc2[4][4];
        #pragma unroll
        for (int ip = 0; ip < 4; ip++) {
            u64 bp = pk(__ldg(&B3[r0 + 2*ip]), __ldg(&B3[r0 + 2*ip + 1]));
            #pragma unroll
            for (int j = 0; j < 4; j++) acc2[ip][j] = bp;
        }
        for (int k = 0; k < 128; k++) {
            const u64* wrow = (const u64*)(sW + k*64 + r0);
            u64 a0 = wrow[0], a1 = wrow[1], a2 = wrow[2], a3 = wrow[3];
            float4 b = *(const float4*)&sT[k*64 + x0];
            u64 b2v[4] = {pkdup(b.x), pkdup(b.y), pkdup(b.z), pkdup(b.w)};
            #pragma unroll
            for (int j = 0; j < 4; j++) {
                acc2[0][j] = f2fma(a0, b2v[j], acc2[0][j]);
                acc2[1][j] = f2fma(a1, b2v[j], acc2[1][j]);
                acc2[2][j] = f2fma(a2, b2v[j], acc2[2][j]);
                acc2[3][j] = f2fma(a3, b2v[j], acc2[3][j]);
            }
        }
        #pragma unroll
        for (int ip = 0; ip < 4; ip++) {
            float2 v0 = up(acc2[ip][0]), v1 = up(acc2[ip][1]);
            float2 v2 = up(acc2[ip][2]), v3 = up(acc2[ip][3]);
            *(float4*)&out[base + (r0 + 2*ip    )*NP + x0] = make_float4(v0.x, v1.x, v2.x, v3.x);
            *(float4*)&out[base + (r0 + 2*ip + 1)*NP + x0] = make_float4(v0.y, v1.y, v2.y, v3.y);
        }
    }
}

// ---------------- S1: row DFT, 2 mode-groups per bc --------------------------
__global__ void __launch_bounds__(264) k_dft_rows() {
    extern __shared__ __align__(16) float2 fy_s[];   // 17 x 264
    const int bc = blockIdx.x, mgrp = blockIdx.y;
    const int m_base = mgrp * 16;
    const int tid = threadIdx.x;
    for (int idx = tid; idx < 17*HP; idx += 264) {
        int ml = idx / HP, y = idx % HP;
        int m = m_base + ml;
        float2 f;
        if (m < 32) f = g_Fy[m*HP + y];
        else { f = g_Fy[32*HP + y]; f.y = -f.y; }
        fy_s[idx] = f;
    }
    __syncthreads();
    const int xt = tid % 66, rq = tid / 66;
    const int x0 = xt * 4, ml0 = rq * 4;
    const bool five = (rq == 3);
    const float* img = g_x + bc*NP;
    u64 acc2[5][4];
    #pragma unroll
    for (int r = 0; r < 5; r++)
        #pragma unroll
        for (int j = 0; j < 4; j++) acc2[r][j] = 0ULL;

    float4 va = __ldg((const float4*)(img + HP + x0));
    float4 vb = __ldg((const float4*)(img + 263*HP + x0));
    for (int y = 1; y <= 131; y++) {
        float4 na = va, nb = vb;
        if (y < 131) {
            na = __ldg((const float4*)(img + (y+1)*HP + x0));
            nb = __ldg((const float4*)(img + (263-y)*HP + x0));
        }
        u64 pd[4] = { pk(va.x+vb.x, va.x-vb.x), pk(va.y+vb.y, va.y-vb.y),
                      pk(va.z+vb.z, va.z-vb.z), pk(va.w+vb.w, va.w-vb.w) };
        #pragma unroll
        for (int r = 0; r < 4; r++) {
            u64 f2 = *(const u64*)&fy_s[(ml0 + r)*HP + y];
            #pragma unroll
            for (int j = 0; j < 4; j++)
                acc2[r][j] = f2fma(pd[j], f2, acc2[r][j]);
        }
        if (five) {
            u64 f2 = *(const u64*)&fy_s[16*HP + y];
            #pragma unroll
            for (int j = 0; j < 4; j++)
                acc2[4][j] = f2fma(pd[j], f2, acc2[4][j]);
        }
        va = na; vb = nb;
    }
    {
        float4 v0   = __ldg((const float4*)(img + x0));
        float4 v132 = __ldg((const float4*)(img + 132*HP + x0));
        u64 z0[4] = {pk(v0.x,0.f),  pk(v0.y,0.f),  pk(v0.z,0.f),  pk(v0.w,0.f)};
        u64 z1[4] = {pk(v132.x,0.f),pk(v132.y,0.f),pk(v132.z,0.f),pk(v132.w,0.f)};
        #pragma unroll
        for (int r = 0; r < 4; r++) {
            u64 c132 = pkdup(fy_s[(ml0 + r)*HP + 132].x);
            #pragma unroll
            for (int j = 0; j < 4; j++)
                acc2[r][j] = f2fma(z1[j], c132, f2add(acc2[r][j], z0[j]));
        }
        if (five) {
            u64 c132 = pkdup(fy_s[16*HP + 132].x);
            #pragma unroll
            for (int j = 0; j < 4; j++)
                acc2[4][j] = f2fma(z1[j], c132, f2add(acc2[4][j], z0[j]));
        }
    }
    #pragma unroll
    for (int r = 0; r < 4; r++) {
        int m = m_base + ml0 + r;
        u64* dst = (u64*)&g_T1[(bc*33 + m)*HP + x0];
        #pragma unroll
        for (int j = 0; j < 4; j++) dst[j] = acc2[r][j];
    }
    if (five) {
        u64* dst = (u64*)&g_T1[(bc*33 + m_base + 16)*HP + x0];
        #pragma unroll
        for (int j = 0; j < 4; j++) dst[j] = acc2[4][j];
    }
}

// ---------------- S2: col DFT, 2 row-groups per bc ---------------------------
__global__ void __launch_bounds__(256) k_dft_cols() {
    extern __shared__ __align__(16) float2 t1s[];
    const int bc = blockIdx.x, by = blockIdx.y;
    const int tid = threadIdx.x;
    const int nrows = by ? 17 : 16;
    const int roff = by * 16 * HP;
    for (int idx = tid; idx < nrows*HP; idx += 256)
        t1s[idx] = g_T1[bc*(33*HP) + roff + idx];
    __syncthreads();
    const int k = tid & 31, rq = tid >> 5;
    u64 P1[2] = {0,0};
    u64 P2[2] = {0,0};
    u64 T1v = 0, T2v = 0;
    const bool do32 = (by == 1) && (rq == 0);
    for (int x = 0; x < HP; x++) {
        float2 f = __ldg(&g_FxT[x*NM + k]);
        u64 fx = pkdup(f.x), fy = pkdup(f.y);
        #pragma unroll
        for (int j = 0; j < 2; j++) {
            u64 pv = *(const u64*)&t1s[(rq + 8*j)*HP + x];
            P1[j] = f2fma(pv, fx, P1[j]);
            P2[j] = f2fma(pv, fy, P2[j]);
        }
        if (do32) {
            u64 pv = *(const u64*)&t1s[16*HP + x];
            T1v = f2fma(pv, fx, T1v);
            T2v = f2fma(pv, fy, T2v);
        }
    }
    #pragma unroll
    for (int j = 0; j < 2; j++) {
        int m = by*16 + rq + 8*j;
        float2 a = up(P1[j]);
        float2 b = up(P2[j]);
        g_xf[(bc*NR + m)*NM + k] = make_float2(a.x - b.y, b.x + a.y);
        if (m >= 1)
            g_xf[(bc*NR + (64 - m))*NM + k] = make_float2(a.x + b.y, b.x - a.y);
    }
    if (do32) {
        float2 a = up(T1v);
        float2 b = up(T2v);
        g_xf[(bc*NR + 32)*NM + k] = make_float2(a.x + b.y, b.x - a.y);
    }
}

// ---------------- S3: channel mix, f32x2 (ar,ai) accumulators ----------------
__global__ void __launch_bounds__(256) k_chanmix(
    const float* __restrict__ w1r, const float* __restrict__ w1i,
    const float* __restrict__ w2r, const float* __restrict__ w2i)
{
    extern __shared__ __align__(16) float2 xs[];
    const int r = blockIdx.y, oh = blockIdx.x;
    const float* wr; const float* wi; int m1;
    if (r < 32) { wr = w1r; wi = w1i; m1 = r; }
    else        { wr = w2r; wi = w2i; m1 = r - 32; }
    const int tid = threadIdx.x;
    for (int idx = tid; idx < NB*NC*NM; idx += 256) {
        int b = idx >> 11, i = (idx >> 5) & 63, kk = idx & 31;
        xs[idx] = g_xf[((b*NC + i)*NR + r)*NM + kk];
    }
    __syncthreads();
    const int k = tid & 31, og = tid >> 5;
    const int o0 = oh*16 + og*2;
    const int woff = m1*NM + k;
    u64 acc[2][4];
    #pragma unroll
    for (int oo = 0; oo < 2; oo++)
        #pragma unroll
        for (int b = 0; b < 4; b++) acc[oo][b] = 0ULL;
    #pragma unroll 2
    for (int i = 0; i < NC; i++) {
        float wre0 = __ldg(&wr[(i*64 + o0    )*1024 + woff]);
        float wim0 = __ldg(&wi[(i*64 + o0    )*1024 + woff]);
        float wre1 = __ldg(&wr[(i*64 + o0 + 1)*1024 + woff]);
        float wim1 = __ldg(&wi[(i*64 + o0 + 1)*1024 + woff]);
        u64 w0a = pk(wre0, wim0), w0b = pk(-wim0, wre0);
        u64 w1a = pk(wre1, wim1), w1b = pk(-wim1, wre1);
        #pragma unroll
        for (int b = 0; b < 4; b++) {
            float2 xv = xs[(b*NC + i)*NM + k];
            u64 xx = pkdup(xv.x), xy = pkdup(xv.y);
            acc[0][b] = f2fma(xx, w0a, f2fma(xy, w0b, acc[0][b]));
            acc[1][b] = f2fma(xx, w1a, f2fma(xy, w1b, acc[1][b]));
        }
    }
    #pragma unroll
    for (int oo = 0; oo < 2; oo++)
        #pragma unroll
        for (int b = 0; b < 4; b++)
            *(u64*)&g_of[((b*NC + o0 + oo)*NR + r)*NM + k] = acc[oo][b];
}

// ---------------- spectral inverse (S4+S5), writes g_sp only -----------------
__global__ void __launch_bounds__(272) k_inv_spec() {
    extern __shared__ __align__(16) float2 sm_inv[];
    float2* os = sm_inv;
    float2* Us = sm_inv + 2048;
    const int bo = blockIdx.x, ch = blockIdx.y;
    const int ybase = ch*68 - ((ch >= 3) ? 4 : 0);
    const int ngrp  = (ch < 2) ? 17 : 16;
    const int tid = threadIdx.x;
    for (int idx = tid; idx < 2048; idx += 272)
        os[idx] = g_of[bo*2048 + idx];
    __syncthreads();
    for (int idx = tid; idx < 31*32; idx += 272) {
        int m = (idx >> 5) + 1, k = idx & 31;
        float2 A = os[m*NM + k], B = os[(64 - m)*NM + k];
        os[m*NM + k]        = make_float2(A.x + B.x, A.y - B.y);
        os[(64 - m)*NM + k] = make_float2(A.y + B.y, A.x - B.x);
    }
    __syncthreads();

    if (tid < 256) {
        const int k = tid & 31, yq = tid >> 5;
        const float2 o0  = os[k];
        const float2 o32 = os[32*NM + k];
        const u64 o0x = pkdup(o0.x), o0y = pkdup(o0.y);
        const u64 p32x = pkdup(o32.x), p32y = pkdup(o32.y), n32y = pkdup(-o32.y);
        for (int g = yq; g < ngrp; g += 8) {
            int y0 = ybase + g*4;
            ulonglong2 C32 = __ldg((const ulonglong2*)&g_Fyc[32*HP + y0]);
            ulonglong2 S32 = __ldg((const ulonglong2*)&g_Fys[32*HP + y0]);
            u64 R01 = f2fma(p32x, C32.x, f2fma(n32y, S32.x, o0x));
            u64 R23 = f2fma(p32x, C32.y, f2fma(n32y, S32.y, o0x));
            u64 I01 = f2fma(p32y, C32.x, f2fma(p32x, S32.x, o0y));
            u64 I23 = f2fma(p32y, C32.y, f2fma(p32x, S32.y, o0y));
            #pragma unroll 4
            for (int m = 1; m <= 31; m++) {
                float2 Ps = os[m*NM + k];
                float2 Qs = os[(64 - m)*NM + k];
                ulonglong2 C = __ldg((const ulonglong2*)&g_Fyc[m*HP + y0]);
                ulonglong2 S = __ldg((const ulonglong2*)&g_Fys[m*HP + y0]);
                u64 px_ = pkdup(Ps.x), py_ = pkdup(Ps.y);
                u64 qx_ = pkdup(Qs.x), qy_ = pkdup(-Qs.y);
                R01 = f2fma(px_, C.x, f2fma(py_, S.x, R01));
                R23 = f2fma(px_, C.y, f2fma(py_, S.y, R23));
                I01 = f2fma(qx_, C.x, f2fma(qy_, S.x, I01));
                I23 = f2fma(qx_, C.y, f2fma(qy_, S.y, I23));
            }
            float2 r01 = up(R01), r23 = up(R23), i01 = up(I01), i23 = up(I23);
            int yl = g*4;
            Us[(yl+0)*NM + k] = make_float2(r01.x*INV_HP, i01.x*INV_HP);
            Us[(yl+1)*NM + k] = make_float2(r01.y*INV_HP, i01.y*INV_HP);
            Us[(yl+2)*NM + k] = make_float2(r23.x*INV_HP, i23.x*INV_HP);
            Us[(yl+3)*NM + k] = make_float2(r23.y*INV_HP, i23.y*INV_HP);
        }
    }
    __syncthreads();

    const int xt = tid % 34, yq2 = tid / 34;
    const int x0 = xt * 4;
    for (int g = yq2; g < ngrp; g += 8) {
        int yl = g*4;
        u64 EO[4][4];
        float u0[4];
        #pragma unroll
        for (int j = 0; j < 4; j++) {
            u0[j] = Us[(yl + j)*NM].x;
            #pragma unroll
            for (int q = 0; q < 4; q++) EO[j][q] = 0ULL;
        }
        for (int k = 1; k < NM; k++) {
            const ulonglong2* fp = (const ulonglong2*)&g_Fx[k*HP + x0];
            ulonglong2 wA = __ldg(fp);
            ulonglong2 wB = __ldg(fp + 1);
            #pragma unroll
            for (int j = 0; j < 4; j++) {
                u64 u = *(const u64*)&Us[(yl + j)*NM + k];
                EO[j][0] = f2fma(u, wA.x, EO[j][0]);
                EO[j][1] = f2fma(u, wA.y, EO[j][1]);
                EO[j][2] = f2fma(u, wB.x, EO[j][2]);
                EO[j][3] = f2fma(u, wB.y, EO[j][3]);
            }
        }
        #pragma unroll
        for (int j = 0; j < 4; j++) {
            int y = ybase + yl + j;
            float2 eo[4] = {up(EO[j][0]), up(EO[j][1]), up(EO[j][2]), up(EO[j][3])};
            if (xt < 33) {
                int idx = bo*NP + y*HP + x0;
                *(float4*)&g_sp[idx] = make_float4(
                    (u0[j] + 2.f*(eo[0].x + eo[0].y))*INV_HP,
                    (u0[j] + 2.f*(eo[1].x + eo[1].y))*INV_HP,
                    (u0[j] + 2.f*(eo[2].x + eo[2].y))*INV_HP,
                    (u0[j] + 2.f*(eo[3].x + eo[3].y))*INV_HP);
                #pragma unroll
                for (int q = 0; q < 4; q++) {
                    if (xt == 0 && q == 0) continue;
                    int xm = 264 - (x0 + q);
                    g_sp[bo*NP + y*HP + xm] = (u0[j] + 2.f*(eo[q].x - eo[q].y))*INV_HP;
                }
            } else {   // x = 132 self-mirror
                g_sp[bo*NP + y*HP + 132] = (u0[j] + 2.f*(eo[0].x + eo[0].y))*INV_HP;
            }
        }
    }
}

// ---------------- join: g_x = g_hbr + g_sp (or cropped out on last layer) ----
template<bool LAST>
__global__ void __launch_bounds__(256) k_add(float* __restrict__ out) {
    int t = blockIdx.x * 256 + threadIdx.x;
    if (!LAST) {
        int i4 = t * 4;                       // over NB*NC*NP floats
        float4 h = *(const float4*)&g_hbr[i4];
        float4 s = *(const float4*)&g_sp[i4];
        *(float4*)&g_x[i4] = make_float4(h.x+s.x, h.y+s.y, h.z+s.z, h.w+s.w);
    } else {
        int x0 = (t & 63) * 4;                // 64 groups of 4 -> x 0..255
        int y  = (t >> 6) & 255;
        int bo = t >> 14;
        int src = bo*NP + y*HP + x0;
        float4 h = *(const float4*)&g_hbr[src];
        float4 s = *(const float4*)&g_sp[src];
        *(float4*)&out[bo*NPIX0 + y*W0 + x0] =
            make_float4(h.x+s.x, h.y+s.y, h.z+s.z, h.w+s.w);
    }
}

// ---------------- launch: two-stream overlap, inv moved to spectral side -----
extern "C" void kernel_launch(void* const* d_in, const int* in_sizes, int n_in,
                              void* d_out, int out_size)
{
    const float* x   = (const float*)d_in[0];
    const float* lw1 = (const float*)d_in[1];
    const float* lb1 = (const float*)d_in[2];
    const float* lw2 = (const float*)d_in[3];
    const float* lb2 = (const float*)d_in[4];
    const float* cw  = (const float*)d_in[5];
    const float* cb  = (const float*)d_in[6];
    const float* m1w = (const float*)d_in[7];
    const float* m1b = (const float*)d_in[8];
    const float* m2w = (const float*)d_in[9];
    const float* m2b = (const float*)d_in[10];
    const float* s1r = (const float*)d_in[11];
    const float* s1i = (const float*)d_in[12];
    const float* s2r = (const float*)d_in[13];
    const float* s2i = (const float*)d_in[14];
    float* out = (float*)d_out;

    float *px, *ph, *pwf, *pw3, *pbf;
    cudaGetSymbolAddress((void**)&px,  g_x);
    cudaGetSymbolAddress((void**)&ph,  g_hbr);
    cudaGetSymbolAddress((void**)&pwf, g_WfT);
    cudaGetSymbolAddress((void**)&pw3, g_W3T);
    cudaGetSymbolAddress((void**)&pbf, g_bf);

    const int LOCAL_SMEM = 20480 * 4;              // 81920 B
    const int DFTR_SMEM  = 17 * HP * 8;            // 35904 B
    const int DFTC_SMEM  = 17 * HP * 8;            // 35904 B
    const int CMIX_SMEM  = NB*NC*NM * 8;           // 65536 B
    const int INV_SMEM   = (2048 + 68*NM) * 8;     // 33792 B
    cudaFuncSetAttribute(k_local,   cudaFuncAttributeMaxDynamicSharedMemorySize, LOCAL_SMEM);
    cudaFuncSetAttribute(k_chanmix, cudaFuncAttributeMaxDynamicSharedMemorySize, CMIX_SMEM);

    static cudaStream_t sp = nullptr;
    static cudaEvent_t evWf, evX[3], evSpec[3], evInit;
    if (!sp) {
        cudaStreamCreateWithFlags(&sp, cudaStreamNonBlocking);
        cudaEventCreateWithFlags(&evWf,   cudaEventDisableTiming);
        cudaEventCreateWithFlags(&evInit, cudaEventDisableTiming);
        for (int i = 0; i < 3; i++) {
            cudaEventCreateWithFlags(&evX[i],    cudaEventDisableTiming);
            cudaEventCreateWithFlags(&evSpec[i], cudaEventDisableTiming);
        }
    }

    // prologue
    cudaEventRecord(evInit, 0);
    cudaStreamWaitEvent(sp, evInit, 0);
    k_wfuse<<<194, 256, 0, sp>>>(cw, cb, m1w, m1b, m2w);
    cudaEventRecord(evWf, sp);

    k_tables<<<132, 256>>>();
    k_zero_pad<<<4160, 256>>>();
    k_lift<<<dim3(256, NB), 256>>>(x, lw1, lb1, lw2, lb2);
    cudaStreamWaitEvent(0, evWf, 0);

    const int ADD_FULL_GRID = (NB*NC*NP) / (256*4);   // 17424
    const int ADD_CROP_GRID = (NB*NC*NPIX0) / (256*4);// 16384

    for (int L = 0; L < 3; L++) {
        cudaEventRecord(evX[L], 0);
        cudaStreamWaitEvent(sp, evX[L], 0);

        // spectral chain + spectral inverse, all on sp
        k_dft_rows<<<dim3(NB*NC, 2), 264, DFTR_SMEM, sp>>>();
        k_dft_cols<<<dim3(NB*NC, 2), 256, DFTC_SMEM, sp>>>();
        k_chanmix<<<dim3(4, 64), 256, CMIX_SMEM, sp>>>(
            s1r + L*SPW, s1i + L*SPW, s2r + L*SPW, s2i + L*SPW);
        k_inv_spec<<<dim3(NB*NC, 4), 272, INV_SMEM, sp>>>();
        cudaEventRecord(evSpec[L], sp);

        // local branch on default stream (concurrent)
        k_local<<<dim3(NP/64, NB), 128, LOCAL_SMEM>>>(
            px, ph, pwf + L*8192, pbf + L*128, pw3 + L*8192, m2b + L*64);

        // join: cheap memory-bound add
        cudaStreamWaitEvent(0, evSpec[L], 0);
        if (L < 2) k_add<false><<<ADD_FULL_GRID, 256>>>(out);
        else       k_add<true ><<<ADD_CROP_GRID, 256>>>(out);
    }
}

// round 14
// speedup vs baseline: 1.1632x; 1.0274x over previous
#include <cuda_runtime.h>
#include <math.h>

#define NB 4
#define CIN 3
#define NC 64
#define H0 256
#define W0 256
#define NPIX0 (H0*W0)
#define HP 264
#define NP (HP*HP)      /* 69696 */
#define NR 64
#define NM 32
#define SPW (64*64*32*32)
#define INV_HP (1.0f/264.0f)

typedef unsigned long long u64;

// ---------------- f32x2 packed-FMA helpers -----------------------------------
__device__ __forceinline__ u64 pk(float lo, float hi) {
    u64 r; asm("mov.b64 %0, {%1, %2};" : "=l"(r) : "f"(lo), "f"(hi)); return r;
}
__device__ __forceinline__ u64 pkdup(float v) { return pk(v, v); }
__device__ __forceinline__ float2 up(u64 v) {
    float lo, hi; asm("mov.b64 {%0, %1}, %2;" : "=f"(lo), "=f"(hi) : "l"(v));
    return make_float2(lo, hi);
}
__device__ __forceinline__ u64 f2fma(u64 a, u64 b, u64 c) {
    u64 d; asm("fma.rn.f32x2 %0, %1, %2, %3;" : "=l"(d) : "l"(a), "l"(b), "l"(c)); return d;
}
__device__ __forceinline__ u64 f2add(u64 a, u64 b) {
    u64 d; asm("add.rn.f32x2 %0, %1, %2;" : "=l"(d) : "l"(a), "l"(b)); return d;
}

// ---------------- scratch ----------------------------------------------------
__device__ float  g_x  [NB*NC*NP];
__device__ float  g_hbr[NB*NC*NP];
__device__ float  g_sp [NB*NC*NP];     // spectral-branch inverse output
__device__ float2 g_T1 [NB*NC*33*HP];
__device__ float2 g_xf [NB*NC*NR*NM];
__device__ float2 g_of [NB*NC*NR*NM];
__device__ float2 g_Fy [NR*HP];
__device__ float2 g_Fx [NM*HP];
__device__ float2 g_FxT[HP*NM];
__device__ float  g_Fyc[33*HP];
__device__ float  g_Fys[33*HP];
__device__ float  g_WfT[3*2*64*64];    // [L][h][k][o64]  (Wf split into o-halves)
__device__ float  g_W3T[3*128*64];     // [L][k][o]
__device__ float  g_bf [3*128];

__device__ __forceinline__ float gelu_exact(float v) {
    return 0.5f * v * (1.0f + erff(v * 0.70710678118654752440f));
}

// ---------------- init --------------------------------------------------------
__global__ void k_tables() {
    int idx = blockIdx.x * 256 + threadIdx.x;
    if (idx < NR*HP) {
        int r = idx / HP, y = idx % HP;
        int ky = (r < 32) ? r : r + 200;
        int m = (ky * y) % HP;
        double a = 6.283185307179586 * (double)m / (double)HP;
        float2 f = make_float2((float)cos(a), (float)(-sin(a)));
        g_Fy[idx] = f;
        if (r <= 32) { g_Fyc[r*HP + y] = f.x; g_Fys[r*HP + y] = f.y; }
    } else if (idx < NR*HP + NM*HP) {
        int j = idx - NR*HP;
        int k = j / HP, xx = j % HP;
        int m = (k * xx) % HP;
        double a = 6.283185307179586 * (double)m / (double)HP;
        float2 f = make_float2((float)cos(a), (float)(-sin(a)));
        g_Fx[j] = f;
        g_FxT[xx*NM + k] = f;
    }
}

__global__ void k_wfuse(const float* __restrict__ cw,  const float* __restrict__ cb,
                        const float* __restrict__ m1w, const float* __restrict__ m1b,
                        const float* __restrict__ m2w) {
    int idx = blockIdx.x * 256 + threadIdx.x;
    if (idx < 3*8192) {
        int L = idx / 8192, r = idx % 8192, k = r >> 7, o = r & 127;
        const float* W2 = m1w + L*8192;
        const float* W1 = cw  + L*4096;
        double s = 0.0;
        for (int j = 0; j < 64; j++) s += (double)W2[o*64 + j] * (double)W1[j*64 + k];
        // split layout: [L][h][k][o64]
        g_WfT[L*8192 + (o >> 6)*4096 + k*64 + (o & 63)] = (float)s;
    } else if (idx < 6*8192) {
        int i = idx - 3*8192;
        int L = i / 8192, r = i % 8192, k = r >> 6, o = r & 63;
        g_W3T[i] = m2w[L*8192 + o*128 + k];
    } else if (idx < 6*8192 + 384) {
        int i = idx - 6*8192;
        int L = i / 128, o = i % 128;
        const float* W2 = m1w + L*8192;
        double s = (double)m1b[L*128 + o];
        for (int j = 0; j < 64; j++) s += (double)W2[o*64 + j] * (double)cb[L*64 + j];
        g_bf[i] = (float)s;
    }
}

// zero only the right/bottom padding bands
__global__ void k_zero_pad() {
    int idx = blockIdx.x * 256 + threadIdx.x;   // 256 images x 4160 px
    int img = idx / 4160, r = idx % 4160;
    int row, col;
    if (r < 2048) { row = r >> 3; col = 256 + (r & 7); }
    else          { int rr = r - 2048; row = 256 + rr / HP; col = rr % HP; }
    g_x[img*NP + row*HP + col] = 0.0f;
}

// ---------------- lift: 5 -> 32 (GELU) -> 64 --------------------------------
__global__ void __launch_bounds__(256) k_lift(
    const float* __restrict__ x,
    const float* __restrict__ w1, const float* __restrict__ b1,
    const float* __restrict__ w2, const float* __restrict__ b2)
{
    __shared__ float sw1[32*5], sb1[32], sw2[64*32], sb2[64];
    for (int i = threadIdx.x; i < 160;  i += 256) sw1[i] = w1[i];
    for (int i = threadIdx.x; i < 32;   i += 256) sb1[i] = b1[i];
    for (int i = threadIdx.x; i < 2048; i += 256) sw2[i] = w2[i];
    for (int i = threadIdx.x; i < 64;   i += 256) sb2[i] = b2[i];
    __syncthreads();
    int b = blockIdx.y;
    int p = blockIdx.x * 256 + threadIdx.x;
    int i = p >> 8, j = p & 255;
    float f[5];
    f[0] = x[(b*CIN + 0)*NPIX0 + p];
    f[1] = x[(b*CIN + 1)*NPIX0 + p];
    f[2] = x[(b*CIN + 2)*NPIX0 + p];
    f[3] = (float)i * (1.0f/255.0f);
    f[4] = (float)j * (1.0f/255.0f);
    float h[32];
    #pragma unroll
    for (int c1 = 0; c1 < 32; c1++) {
        float v = sb1[c1];
        #pragma unroll
        for (int q = 0; q < 5; q++) v = fmaf(sw1[c1*5+q], f[q], v);
        h[c1] = gelu_exact(v);
    }
    int base = b*NC*NP + i*HP + j;
    for (int c2 = 0; c2 < 64; c2++) {
        float v = sb2[c2];
        #pragma unroll
        for (int c1 = 0; c1 < 32; c1++) v = fmaf(sw2[c2*32+c1], h[c1], v);
        g_x[base + c2*NP] = v;
    }
}

// ---------------- fused local branch, f32x2, 128 threads, 64KB smem ---------
// smem: sX 4096f | sT 8192f | sW 4096f (weights streamed in 16KB panels)
__global__ void __launch_bounds__(128, 3) k_local(
    const float* __restrict__ in, float* __restrict__ out,
    const float* __restrict__ WfT, const float* __restrict__ Bf,
    const float* __restrict__ W3T, const float* __restrict__ B3)
{
    extern __shared__ __align__(16) float sm_local[];
    float* sX = sm_local;            // 64x64
    float* sT = sm_local + 4096;     // 128x64
    float* sW = sm_local + 12288;    // 64x64 panel
    const int tid = threadIdx.x;
    const int ty = tid >> 4, tx = tid & 15;
    const int r0 = ty * 8, x0 = tx * 4;
    const int base = blockIdx.y * (NC*NP) + blockIdx.x * 64;

    #pragma unroll
    for (int i = 0; i < 32; i++) {
        int idx = tid + i*128;
        sX[idx] = in[base + (idx >> 6)*NP + (idx & 63)];
    }

    // ---- stage A: T = gelu(Wf X + bf), two o-halves, weights streamed
    #pragma unroll
    for (int h = 0; h < 2; h++) {
        #pragma unroll
        for (int i = 0; i < 32; i++) {
            int idx = tid + i*128;
            sW[idx] = WfT[h*4096 + idx];     // [k][o64] panel
        }
        __syncthreads();
        u64 acc2[4][4];
        #pragma unroll
        for (int ip = 0; ip < 4; ip++) {
            u64 bp = pk(__ldg(&Bf[h*64 + r0 + 2*ip]), __ldg(&Bf[h*64 + r0 + 2*ip + 1]));
            #pragma unroll
            for (int j = 0; j < 4; j++) acc2[ip][j] = bp;
        }
        for (int k = 0; k < 64; k++) {
            const u64* wrow = (const u64*)(sW + k*64 + r0);
            u64 a0 = wrow[0], a1 = wrow[1], a2 = wrow[2], a3 = wrow[3];
            float4 b = *(const float4*)&sX[k*64 + x0];
            u64 b2v[4] = {pkdup(b.x), pkdup(b.y), pkdup(b.z), pkdup(b.w)};
            #pragma unroll
            for (int j = 0; j < 4; j++) {
                acc2[0][j] = f2fma(a0, b2v[j], acc2[0][j]);
                acc2[1][j] = f2fma(a1, b2v[j], acc2[1][j]);
                acc2[2][j] = f2fma(a2, b2v[j], acc2[2][j]);
                acc2[3][j] = f2fma(a3, b2v[j], acc2[3][j]);
            }
        }
        #pragma unroll
        for (int ip = 0; ip < 4; ip++) {
            float2 v0 = up(acc2[ip][0]), v1 = up(acc2[ip][1]);
            float2 v2 = up(acc2[ip][2]), v3 = up(acc2[ip][3]);
            *(float4*)&sT[(h*64 + r0 + 2*ip    )*64 + x0] =
                make_float4(gelu_exact(v0.x), gelu_exact(v1.x), gelu_exact(v2.x), gelu_exact(v3.x));
            *(float4*)&sT[(h*64 + r0 + 2*ip + 1)*64 + x0] =
                make_float4(gelu_exact(v0.y), gelu_exact(v1.y), gelu_exact(v2.y), gelu_exact(v3.y));
        }
        __syncthreads();   // sT half written; sW free for next panel
    }

    // ---- stage B: OUT = W3 T + b3 (K=128), two K-halves, weights streamed
    {
        u64 acc2[4][4];
        #pragma unroll
        for (int ip = 0; ip < 4; ip++) {
            u64 bp = pk(__ldg(&B3[r0 + 2*ip]), __ldg(&B3[r0 + 2*ip + 1]));
            #pragma unroll
            for (int j = 0; j < 4; j++) acc2[ip][j] = bp;
        }
        #pragma unroll
        for (int kh = 0; kh < 2; kh++) {
            #pragma unroll
            for (int i = 0; i < 32; i++) {
                int idx = tid + i*128;
                sW[idx] = W3T[kh*4096 + idx];   // rows kh*64..kh*64+63
            }
            __syncthreads();
            for (int k = 0; k < 64; k++) {
                const u64* wrow = (const u64*)(sW + k*64 + r0);
                u64 a0 = wrow[0], a1 = wrow[1], a2 = wrow[2], a3 = wrow[3];
                float4 b = *(const float4*)&sT[(kh*64 + k)*64 + x0];
                u64 b2v[4] = {pkdup(b.x), pkdup(b.y), pkdup(b.z), pkdup(b.w)};
                #pragma unroll
                for (int j = 0; j < 4; j++) {
                    acc2[0][j] = f2fma(a0, b2v[j], acc2[0][j]);
                    acc2[1][j] = f2fma(a1, b2v[j], acc2[1][j]);
                    acc2[2][j] = f2fma(a2, b2v[j], acc2[2][j]);
                    acc2[3][j] = f2fma(a3, b2v[j], acc2[3][j]);
                }
            }
            if (kh == 0) __syncthreads();       // sW free for second panel
        }
        #pragma unroll
        for (int ip = 0; ip < 4; ip++) {
            float2 v0 = up(acc2[ip][0]), v1 = up(acc2[ip][1]);
            float2 v2 = up(acc2[ip][2]), v3 = up(acc2[ip][3]);
            *(float4*)&out[base + (r0 + 2*ip    )*NP + x0] = make_float4(v0.x, v1.x, v2.x, v3.x);
            *(float4*)&out[base + (r0 + 2*ip + 1)*NP + x0] = make_float4(v0.y, v1.y, v2.y, v3.y);
        }
    }
}

// ---------------- S1: row DFT, 2 mode-groups per bc --------------------------
__global__ void __launch_bounds__(264) k_dft_rows() {
    extern __shared__ __align__(16) float2 fy_s[];   // 17 x 264
    const int bc = blockIdx.x, mgrp = blockIdx.y;
    const int m_base = mgrp * 16;
    const int tid = threadIdx.x;
    for (int idx = tid; idx < 17*HP; idx += 264) {
        int ml = idx / HP, y = idx % HP;
        int m = m_base + ml;
        float2 f;
        if (m < 32) f = g_Fy[m*HP + y];
        else { f = g_Fy[32*HP + y]; f.y = -f.y; }
        fy_s[idx] = f;
    }
    __syncthreads();
    const int xt = tid % 66, rq = tid / 66;
    const int x0 = xt * 4, ml0 = rq * 4;
    const bool five = (rq == 3);
    const float* img = g_x + bc*NP;
    u64 acc2[5][4];
    #pragma unroll
    for (int r = 0; r < 5; r++)
        #pragma unroll
        for (int j = 0; j < 4; j++) acc2[r][j] = 0ULL;

    float4 va = __ldg((const float4*)(img + HP + x0));
    float4 vb = __ldg((const float4*)(img + 263*HP + x0));
    for (int y = 1; y <= 131; y++) {
        float4 na = va, nb = vb;
        if (y < 131) {
            na = __ldg((const float4*)(img + (y+1)*HP + x0));
            nb = __ldg((const float4*)(img + (263-y)*HP + x0));
        }
        u64 pd[4] = { pk(va.x+vb.x, va.x-vb.x), pk(va.y+vb.y, va.y-vb.y),
                      pk(va.z+vb.z, va.z-vb.z), pk(va.w+vb.w, va.w-vb.w) };
        #pragma unroll
        for (int r = 0; r < 4; r++) {
            u64 f2 = *(const u64*)&fy_s[(ml0 + r)*HP + y];
            #pragma unroll
            for (int j = 0; j < 4; j++)
                acc2[r][j] = f2fma(pd[j], f2, acc2[r][j]);
        }
        if (five) {
            u64 f2 = *(const u64*)&fy_s[16*HP + y];
            #pragma unroll
            for (int j = 0; j < 4; j++)
                acc2[4][j] = f2fma(pd[j], f2, acc2[4][j]);
        }
        va = na; vb = nb;
    }
    {
        float4 v0   = __ldg((const float4*)(img + x0));
        float4 v132 = __ldg((const float4*)(img + 132*HP + x0));
        u64 z0[4] = {pk(v0.x,0.f),  pk(v0.y,0.f),  pk(v0.z,0.f),  pk(v0.w,0.f)};
        u64 z1[4] = {pk(v132.x,0.f),pk(v132.y,0.f),pk(v132.z,0.f),pk(v132.w,0.f)};
        #pragma unroll
        for (int r = 0; r < 4; r++) {
            u64 c132 = pkdup(fy_s[(ml0 + r)*HP + 132].x);
            #pragma unroll
            for (int j = 0; j < 4; j++)
                acc2[r][j] = f2fma(z1[j], c132, f2add(acc2[r][j], z0[j]));
        }
        if (five) {
            u64 c132 = pkdup(fy_s[16*HP + 132].x);
            #pragma unroll
            for (int j = 0; j < 4; j++)
                acc2[4][j] = f2fma(z1[j], c132, f2add(acc2[4][j], z0[j]));
        }
    }
    #pragma unroll
    for (int r = 0; r < 4; r++) {
        int m = m_base + ml0 + r;
        u64* dst = (u64*)&g_T1[(bc*33 + m)*HP + x0];
        #pragma unroll
        for (int j = 0; j < 4; j++) dst[j] = acc2[r][j];
    }
    if (five) {
        u64* dst = (u64*)&g_T1[(bc*33 + m_base + 16)*HP + x0];
        #pragma unroll
        for (int j = 0; j < 4; j++) dst[j] = acc2[4][j];
    }
}

// ---------------- S2: col DFT, 2 row-groups per bc ---------------------------
__global__ void __launch_bounds__(256) k_dft_cols() {
    extern __shared__ __align__(16) float2 t1s[];
    const int bc = blockIdx.x, by = blockIdx.y;
    const int tid = threadIdx.x;
    const int nrows = by ? 17 : 16;
    const int roff = by * 16 * HP;
    for (int idx = tid; idx < nrows*HP; idx += 256)
        t1s[idx] = g_T1[bc*(33*HP) + roff + idx];
    __syncthreads();
    const int k = tid & 31, rq = tid >> 5;
    u64 P1[2] = {0,0};
    u64 P2[2] = {0,0};
    u64 T1v = 0, T2v = 0;
    const bool do32 = (by == 1) && (rq == 0);
    for (int x = 0; x < HP; x++) {
        float2 f = __ldg(&g_FxT[x*NM + k]);
        u64 fx = pkdup(f.x), fy = pkdup(f.y);
        #pragma unroll
        for (int j = 0; j < 2; j++) {
            u64 pv = *(const u64*)&t1s[(rq + 8*j)*HP + x];
            P1[j] = f2fma(pv, fx, P1[j]);
            P2[j] = f2fma(pv, fy, P2[j]);
        }
        if (do32) {
            u64 pv = *(const u64*)&t1s[16*HP + x];
            T1v = f2fma(pv, fx, T1v);
            T2v = f2fma(pv, fy, T2v);
        }
    }
    #pragma unroll
    for (int j = 0; j < 2; j++) {
        int m = by*16 + rq + 8*j;
        float2 a = up(P1[j]);
        float2 b = up(P2[j]);
        g_xf[(bc*NR + m)*NM + k] = make_float2(a.x - b.y, b.x + a.y);
        if (m >= 1)
            g_xf[(bc*NR + (64 - m))*NM + k] = make_float2(a.x + b.y, b.x - a.y);
    }
    if (do32) {
        float2 a = up(T1v);
        float2 b = up(T2v);
        g_xf[(bc*NR + 32)*NM + k] = make_float2(a.x + b.y, b.x - a.y);
    }
}

// ---------------- S3: channel mix, f32x2 (ar,ai) accumulators ----------------
__global__ void __launch_bounds__(256) k_chanmix(
    const float* __restrict__ w1r, const float* __restrict__ w1i,
    const float* __restrict__ w2r, const float* __restrict__ w2i)
{
    extern __shared__ __align__(16) float2 xs[];
    const int r = blockIdx.y, oh = blockIdx.x;
    const float* wr; const float* wi; int m1;
    if (r < 32) { wr = w1r; wi = w1i; m1 = r; }
    else        { wr = w2r; wi = w2i; m1 = r - 32; }
    const int tid = threadIdx.x;
    for (int idx = tid; idx < NB*NC*NM; idx += 256) {
        int b = idx >> 11, i = (idx >> 5) & 63, kk = idx & 31;
        xs[idx] = g_xf[((b*NC + i)*NR + r)*NM + kk];
    }
    __syncthreads();
    const int k = tid & 31, og = tid >> 5;
    const int o0 = oh*16 + og*2;
    const int woff = m1*NM + k;
    u64 acc[2][4];
    #pragma unroll
    for (int oo = 0; oo < 2; oo++)
        #pragma unroll
        for (int b = 0; b < 4; b++) acc[oo][b] = 0ULL;
    #pragma unroll 2
    for (int i = 0; i < NC; i++) {
        float wre0 = __ldg(&wr[(i*64 + o0    )*1024 + woff]);
        float wim0 = __ldg(&wi[(i*64 + o0    )*1024 + woff]);
        float wre1 = __ldg(&wr[(i*64 + o0 + 1)*1024 + woff]);
        float wim1 = __ldg(&wi[(i*64 + o0 + 1)*1024 + woff]);
        u64 w0a = pk(wre0, wim0), w0b = pk(-wim0, wre0);
        u64 w1a = pk(wre1, wim1), w1b = pk(-wim1, wre1);
        #pragma unroll
        for (int b = 0; b < 4; b++) {
            float2 xv = xs[(b*NC + i)*NM + k];
            u64 xx = pkdup(xv.x), xy = pkdup(xv.y);
            acc[0][b] = f2fma(xx, w0a, f2fma(xy, w0b, acc[0][b]));
            acc[1][b] = f2fma(xx, w1a, f2fma(xy, w1b, acc[1][b]));
        }
    }
    #pragma unroll
    for (int oo = 0; oo < 2; oo++)
        #pragma unroll
        for (int b = 0; b < 4; b++)
            *(u64*)&g_of[((b*NC + o0 + oo)*NR + r)*NM + k] = acc[oo][b];
}

// ---------------- spectral inverse (S4+S5), writes g_sp only -----------------
__global__ void __launch_bounds__(272) k_inv_spec() {
    extern __shared__ __align__(16) float2 sm_inv[];
    float2* os = sm_inv;
    float2* Us = sm_inv + 2048;
    const int bo = blockIdx.x, ch = blockIdx.y;
    const int ybase = ch*68 - ((ch >= 3) ? 4 : 0);
    const int ngrp  = (ch < 2) ? 17 : 16;
    const int tid = threadIdx.x;
    for (int idx = tid; idx < 2048; idx += 272)
        os[idx] = g_of[bo*2048 + idx];
    __syncthreads();
    for (int idx = tid; idx < 31*32; idx += 272) {
        int m = (idx >> 5) + 1, k = idx & 31;
        float2 A = os[m*NM + k], B = os[(64 - m)*NM + k];
        os[m*NM + k]        = make_float2(A.x + B.x, A.y - B.y);
        os[(64 - m)*NM + k] = make_float2(A.y + B.y, A.x - B.x);
    }
    __syncthreads();

    if (tid < 256) {
        const int k = tid & 31, yq = tid >> 5;
        const float2 o0  = os[k];
        const float2 o32 = os[32*NM + k];
        const u64 o0x = pkdup(o0.x), o0y = pkdup(o0.y);
        const u64 p32x = pkdup(o32.x), p32y = pkdup(o32.y), n32y = pkdup(-o32.y);
        for (int g = yq; g < ngrp; g += 8) {
            int y0 = ybase + g*4;
            ulonglong2 C32 = __ldg((const ulonglong2*)&g_Fyc[32*HP + y0]);
            ulonglong2 S32 = __ldg((const ulonglong2*)&g_Fys[32*HP + y0]);
            u64 R01 = f2fma(p32x, C32.x, f2fma(n32y, S32.x, o0x));
            u64 R23 = f2fma(p32x, C32.y, f2fma(n32y, S32.y, o0x));
            u64 I01 = f2fma(p32y, C32.x, f2fma(p32x, S32.x, o0y));
            u64 I23 = f2fma(p32y, C32.y, f2fma(p32x, S32.y, o0y));
            #pragma unroll 4
            for (int m = 1; m <= 31; m++) {
                float2 Ps = os[m*NM + k];
                float2 Qs = os[(64 - m)*NM + k];
                ulonglong2 C = __ldg((const ulonglong2*)&g_Fyc[m*HP + y0]);
                ulonglong2 S = __ldg((const ulonglong2*)&g_Fys[m*HP + y0]);
                u64 px_ = pkdup(Ps.x), py_ = pkdup(Ps.y);
                u64 qx_ = pkdup(Qs.x), qy_ = pkdup(-Qs.y);
                R01 = f2fma(px_, C.x, f2fma(py_, S.x, R01));
                R23 = f2fma(px_, C.y, f2fma(py_, S.y, R23));
                I01 = f2fma(qx_, C.x, f2fma(qy_, S.x, I01));
                I23 = f2fma(qx_, C.y, f2fma(qy_, S.y, I23));
            }
            float2 r01 = up(R01), r23 = up(R23), i01 = up(I01), i23 = up(I23);
            int yl = g*4;
            Us[(yl+0)*NM + k] = make_float2(r01.x*INV_HP, i01.x*INV_HP);
            Us[(yl+1)*NM + k] = make_float2(r01.y*INV_HP, i01.y*INV_HP);
            Us[(yl+2)*NM + k] = make_float2(r23.x*INV_HP, i23.x*INV_HP);
            Us[(yl+3)*NM + k] = make_float2(r23.y*INV_HP, i23.y*INV_HP);
        }
    }
    __syncthreads();

    const int xt = tid % 34, yq2 = tid / 34;
    const int x0 = xt * 4;
    for (int g = yq2; g < ngrp; g += 8) {
        int yl = g*4;
        u64 EO[4][4];
        float u0[4];
        #pragma unroll
        for (int j = 0; j < 4; j++) {
            u0[j] = Us[(yl + j)*NM].x;
            #pragma unroll
            for (int q = 0; q < 4; q++) EO[j][q] = 0ULL;
        }
        for (int k = 1; k < NM; k++) {
            const ulonglong2* fp = (const ulonglong2*)&g_Fx[k*HP + x0];
            ulonglong2 wA = __ldg(fp);
            ulonglong2 wB = __ldg(fp + 1);
            #pragma unroll
            for (int j = 0; j < 4; j++) {
                u64 u = *(const u64*)&Us[(yl + j)*NM + k];
                EO[j][0] = f2fma(u, wA.x, EO[j][0]);
                EO[j][1] = f2fma(u, wA.y, EO[j][1]);
                EO[j][2] = f2fma(u, wB.x, EO[j][2]);
                EO[j][3] = f2fma(u, wB.y, EO[j][3]);
            }
        }
        #pragma unroll
        for (int j = 0; j < 4; j++) {
            int y = ybase + yl + j;
            float2 eo[4] = {up(EO[j][0]), up(EO[j][1]), up(EO[j][2]), up(EO[j][3])};
            if (xt < 33) {
                int idx = bo*NP + y*HP + x0;
                *(float4*)&g_sp[idx] = make_float4(
                    (u0[j] + 2.f*(eo[0].x + eo[0].y))*INV_HP,
                    (u0[j] + 2.f*(eo[1].x + eo[1].y))*INV_HP,
                    (u0[j] + 2.f*(eo[2].x + eo[2].y))*INV_HP,
                    (u0[j] + 2.f*(eo[3].x + eo[3].y))*INV_HP);
                #pragma unroll
                for (int q = 0; q < 4; q++) {
                    if (xt == 0 && q == 0) continue;
                    int xm = 264 - (x0 + q);
                    g_sp[bo*NP + y*HP + xm] = (u0[j] + 2.f*(eo[q].x - eo[q].y))*INV_HP;
                }
            } else {   // x = 132 self-mirror
                g_sp[bo*NP + y*HP + 132] = (u0[j] + 2.f*(eo[0].x + eo[0].y))*INV_HP;
            }
        }
    }
}

// ---------------- join: g_x = g_hbr + g_sp (or cropped out on last layer) ----
template<bool LAST>
__global__ void __launch_bounds__(256) k_add(float* __restrict__ out) {
    int t = blockIdx.x * 256 + threadIdx.x;
    if (!LAST) {
        int i4 = t * 4;
        float4 h = *(const float4*)&g_hbr[i4];
        float4 s = *(const float4*)&g_sp[i4];
        *(float4*)&g_x[i4] = make_float4(h.x+s.x, h.y+s.y, h.z+s.z, h.w+s.w);
    } else {
        int x0 = (t & 63) * 4;
        int y  = (t >> 6) & 255;
        int bo = t >> 14;
        int src = bo*NP + y*HP + x0;
        float4 h = *(const float4*)&g_hbr[src];
        float4 s = *(const float4*)&g_sp[src];
        *(float4*)&out[bo*NPIX0 + y*W0 + x0] =
            make_float4(h.x+s.x, h.y+s.y, h.z+s.z, h.w+s.w);
    }
}

// ---------------- launch: two-stream overlap ----------------------------------
extern "C" void kernel_launch(void* const* d_in, const int* in_sizes, int n_in,
                              void* d_out, int out_size)
{
    const float* x   = (const float*)d_in[0];
    const float* lw1 = (const float*)d_in[1];
    const float* lb1 = (const float*)d_in[2];
    const float* lw2 = (const float*)d_in[3];
    const float* lb2 = (const float*)d_in[4];
    const float* cw  = (const float*)d_in[5];
    const float* cb  = (const float*)d_in[6];
    const float* m1w = (const float*)d_in[7];
    const float* m1b = (const float*)d_in[8];
    const float* m2w = (const float*)d_in[9];
    const float* m2b = (const float*)d_in[10];
    const float* s1r = (const float*)d_in[11];
    const float* s1i = (const float*)d_in[12];
    const float* s2r = (const float*)d_in[13];
    const float* s2i = (const float*)d_in[14];
    float* out = (float*)d_out;

    float *px, *ph, *pwf, *pw3, *pbf;
    cudaGetSymbolAddress((void**)&px,  g_x);
    cudaGetSymbolAddress((void**)&ph,  g_hbr);
    cudaGetSymbolAddress((void**)&pwf, g_WfT);
    cudaGetSymbolAddress((void**)&pw3, g_W3T);
    cudaGetSymbolAddress((void**)&pbf, g_bf);

    const int LOCAL_SMEM = 16384 * 4;              // 65536 B -> 3 blocks/SM
    const int DFTR_SMEM  = 17 * HP * 8;            // 35904 B
    const int DFTC_SMEM  = 17 * HP * 8;            // 35904 B
    const int CMIX_SMEM  = NB*NC*NM * 8;           // 65536 B
    const int INV_SMEM   = (2048 + 68*NM) * 8;     // 33792 B
    cudaFuncSetAttribute(k_local,   cudaFuncAttributeMaxDynamicSharedMemorySize, LOCAL_SMEM);
    cudaFuncSetAttribute(k_chanmix, cudaFuncAttributeMaxDynamicSharedMemorySize, CMIX_SMEM);

    static cudaStream_t sp = nullptr;
    static cudaEvent_t evWf, evX[3], evSpec[3], evInit;
    if (!sp) {
        cudaStreamCreateWithFlags(&sp, cudaStreamNonBlocking);
        cudaEventCreateWithFlags(&evWf,   cudaEventDisableTiming);
        cudaEventCreateWithFlags(&evInit, cudaEventDisableTiming);
        for (int i = 0; i < 3; i++) {
            cudaEventCreateWithFlags(&evX[i],    cudaEventDisableTiming);
            cudaEventCreateWithFlags(&evSpec[i], cudaEventDisableTiming);
        }
    }

    // prologue
    cudaEventRecord(evInit, 0);
    cudaStreamWaitEvent(sp, evInit, 0);
    k_wfuse<<<194, 256, 0, sp>>>(cw, cb, m1w, m1b, m2w);
    cudaEventRecord(evWf, sp);

    k_tables<<<132, 256>>>();
    k_zero_pad<<<4160, 256>>>();
    k_lift<<<dim3(256, NB), 256>>>(x, lw1, lb1, lw2, lb2);
    cudaStreamWaitEvent(0, evWf, 0);

    const int ADD_FULL_GRID = (NB*NC*NP) / (256*4);   // 17424
    const int ADD_CROP_GRID = (NB*NC*NPIX0) / (256*4);// 16384

    for (int L = 0; L < 3; L++) {
        cudaEventRecord(evX[L], 0);
        cudaStreamWaitEvent(sp, evX[L], 0);

        // spectral chain + spectral inverse, all on sp
        k_dft_rows<<<dim3(NB*NC, 2), 264, DFTR_SMEM, sp>>>();
        k_dft_cols<<<dim3(NB*NC, 2), 256, DFTC_SMEM, sp>>>();
        k_chanmix<<<dim3(4, 64), 256, CMIX_SMEM, sp>>>(
            s1r + L*SPW, s1i + L*SPW, s2r + L*SPW, s2i + L*SPW);
        k_inv_spec<<<dim3(NB*NC, 4), 272, INV_SMEM, sp>>>();
        cudaEventRecord(evSpec[L], sp);

        // local branch on default stream (concurrent)
        k_local<<<dim3(NP/64, NB), 128, LOCAL_SMEM>>>(
            px, ph, pwf + L*8192, pbf + L*128, pw3 + L*8192, m2b + L*64);

        // join
        cudaStreamWaitEvent(0, evSpec[L], 0);
        if (L < 2) k_add<false><<<ADD_FULL_GRID, 256>>>(out);
        else       k_add<true ><<<ADD_CROP_GRID, 256>>>(out);
    }
}

// round 15
// speedup vs baseline: 1.1664x; 1.0027x over previous
#include <cuda_runtime.h>
#include <math.h>

#define NB 4
#define CIN 3
#define NC 64
#define H0 256
#define W0 256
#define NPIX0 (H0*W0)
#define HP 264
#define NP (HP*HP)      /* 69696 */
#define NR 64
#define NM 32
#define SPW (64*64*32*32)
#define INV_HP (1.0f/264.0f)

typedef unsigned long long u64;

// ---------------- f32x2 packed-FMA helpers -----------------------------------
__device__ __forceinline__ u64 pk(float lo, float hi) {
    u64 r; asm("mov.b64 %0, {%1, %2};" : "=l"(r) : "f"(lo), "f"(hi)); return r;
}
__device__ __forceinline__ u64 pkdup(float v) { return pk(v, v); }
__device__ __forceinline__ float2 up(u64 v) {
    float lo, hi; asm("mov.b64 {%0, %1}, %2;" : "=f"(lo), "=f"(hi) : "l"(v));
    return make_float2(lo, hi);
}
__device__ __forceinline__ u64 f2fma(u64 a, u64 b, u64 c) {
    u64 d; asm("fma.rn.f32x2 %0, %1, %2, %3;" : "=l"(d) : "l"(a), "l"(b), "l"(c)); return d;
}
__device__ __forceinline__ u64 f2add(u64 a, u64 b) {
    u64 d; asm("add.rn.f32x2 %0, %1, %2;" : "=l"(d) : "l"(a), "l"(b)); return d;
}

// ---------------- scratch ----------------------------------------------------
__device__ float  g_x  [NB*NC*NP];
__device__ float  g_hbr[NB*NC*NP];
__device__ float  g_sp [NB*NC*NP];     // spectral-branch inverse output
__device__ float2 g_T1 [NB*NC*33*HP];
__device__ float2 g_xf [NB*NC*NR*NM];
__device__ float2 g_of [NB*NC*NR*NM];
__device__ float2 g_Fy [NR*HP];
__device__ float2 g_Fx [NM*HP];
__device__ float2 g_FxT[HP*NM];
__device__ float  g_Fyc[33*HP];
__device__ float  g_Fys[33*HP];
__device__ float  g_WfT[3*2*64*64];    // [L][h][k][o64]  (Wf split into o-halves)
__device__ float  g_W3T[3*128*64];     // [L][k][o]
__device__ float  g_bf [3*128];

__device__ __forceinline__ float gelu_exact(float v) {
    return 0.5f * v * (1.0f + erff(v * 0.70710678118654752440f));
}

// ---------------- init --------------------------------------------------------
__global__ void k_tables() {
    int idx = blockIdx.x * 256 + threadIdx.x;
    if (idx < NR*HP) {
        int r = idx / HP, y = idx % HP;
        int ky = (r < 32) ? r : r + 200;
        int m = (ky * y) % HP;
        double a = 6.283185307179586 * (double)m / (double)HP;
        float2 f = make_float2((float)cos(a), (float)(-sin(a)));
        g_Fy[idx] = f;
        if (r <= 32) { g_Fyc[r*HP + y] = f.x; g_Fys[r*HP + y] = f.y; }
    } else if (idx < NR*HP + NM*HP) {
        int j = idx - NR*HP;
        int k = j / HP, xx = j % HP;
        int m = (k * xx) % HP;
        double a = 6.283185307179586 * (double)m / (double)HP;
        float2 f = make_float2((float)cos(a), (float)(-sin(a)));
        g_Fx[j] = f;
        g_FxT[xx*NM + k] = f;
    }
}

__global__ void k_wfuse(const float* __restrict__ cw,  const float* __restrict__ cb,
                        const float* __restrict__ m1w, const float* __restrict__ m1b,
                        const float* __restrict__ m2w) {
    int idx = blockIdx.x * 256 + threadIdx.x;
    if (idx < 3*8192) {
        int L = idx / 8192, r = idx % 8192, k = r >> 7, o = r & 127;
        const float* W2 = m1w + L*8192;
        const float* W1 = cw  + L*4096;
        double s = 0.0;
        for (int j = 0; j < 64; j++) s += (double)W2[o*64 + j] * (double)W1[j*64 + k];
        g_WfT[L*8192 + (o >> 6)*4096 + k*64 + (o & 63)] = (float)s;
    } else if (idx < 6*8192) {
        int i = idx - 3*8192;
        int L = i / 8192, r = i % 8192, k = r >> 6, o = r & 63;
        g_W3T[i] = m2w[L*8192 + o*128 + k];
    } else if (idx < 6*8192 + 384) {
        int i = idx - 6*8192;
        int L = i / 128, o = i % 128;
        const float* W2 = m1w + L*8192;
        double s = (double)m1b[L*128 + o];
        for (int j = 0; j < 64; j++) s += (double)W2[o*64 + j] * (double)cb[L*64 + j];
        g_bf[i] = (float)s;
    }
}

// zero only the right/bottom padding bands
__global__ void k_zero_pad() {
    int idx = blockIdx.x * 256 + threadIdx.x;   // 256 images x 4160 px
    int img = idx / 4160, r = idx % 4160;
    int row, col;
    if (r < 2048) { row = r >> 3; col = 256 + (r & 7); }
    else          { int rr = r - 2048; row = 256 + rr / HP; col = rr % HP; }
    g_x[img*NP + row*HP + col] = 0.0f;
}

// ---------------- lift: 5 -> 32 (GELU) -> 64 --------------------------------
__global__ void __launch_bounds__(256) k_lift(
    const float* __restrict__ x,
    const float* __restrict__ w1, const float* __restrict__ b1,
    const float* __restrict__ w2, const float* __restrict__ b2)
{
    __shared__ float sw1[32*5], sb1[32], sw2[64*32], sb2[64];
    for (int i = threadIdx.x; i < 160;  i += 256) sw1[i] = w1[i];
    for (int i = threadIdx.x; i < 32;   i += 256) sb1[i] = b1[i];
    for (int i = threadIdx.x; i < 2048; i += 256) sw2[i] = w2[i];
    for (int i = threadIdx.x; i < 64;   i += 256) sb2[i] = b2[i];
    __syncthreads();
    int b = blockIdx.y;
    int p = blockIdx.x * 256 + threadIdx.x;
    int i = p >> 8, j = p & 255;
    float f[5];
    f[0] = x[(b*CIN + 0)*NPIX0 + p];
    f[1] = x[(b*CIN + 1)*NPIX0 + p];
    f[2] = x[(b*CIN + 2)*NPIX0 + p];
    f[3] = (float)i * (1.0f/255.0f);
    f[4] = (float)j * (1.0f/255.0f);
    float h[32];
    #pragma unroll
    for (int c1 = 0; c1 < 32; c1++) {
        float v = sb1[c1];
        #pragma unroll
        for (int q = 0; q < 5; q++) v = fmaf(sw1[c1*5+q], f[q], v);
        h[c1] = gelu_exact(v);
    }
    int base = b*NC*NP + i*HP + j;
    for (int c2 = 0; c2 < 64; c2++) {
        float v = sb2[c2];
        #pragma unroll
        for (int c1 = 0; c1 < 32; c1++) v = fmaf(sw2[c2*32+c1], h[c1], v);
        g_x[base + c2*NP] = v;
    }
}

// ---------------- fused local branch, f32x2, 128 threads, 48KB smem ---------
// Interleaved halves: stage A half-h -> sT(64x64) -> stage B partial(K half-h).
// smem: sX 4096f | sT 4096f | sW 4096f = 49152 B -> 4 blocks/SM.
__global__ void __launch_bounds__(128, 4) k_local(
    const float* __restrict__ in, float* __restrict__ out,
    const float* __restrict__ WfT, const float* __restrict__ Bf,
    const float* __restrict__ W3T, const float* __restrict__ B3)
{
    extern __shared__ __align__(16) float sm_local[];
    float* sX = sm_local;            // 64x64
    float* sT = sm_local + 4096;     // 64x64 (current half of T)
    float* sW = sm_local + 8192;     // 64x64 panel
    const int tid = threadIdx.x;
    const int ty = tid >> 4, tx = tid & 15;
    const int r0 = ty * 8, x0 = tx * 4;
    const int base = blockIdx.y * (NC*NP) + blockIdx.x * 64;

    #pragma unroll
    for (int i = 0; i < 32; i++) {
        int idx = tid + i*128;
        sX[idx] = in[base + (idx >> 6)*NP + (idx & 63)];
    }

    // stage-B accumulators live across both halves
    u64 accB[4][4];
    #pragma unroll
    for (int ip = 0; ip < 4; ip++) {
        u64 bp = pk(__ldg(&B3[r0 + 2*ip]), __ldg(&B3[r0 + 2*ip + 1]));
        #pragma unroll
        for (int j = 0; j < 4; j++) accB[ip][j] = bp;
    }

    #pragma unroll
    for (int h = 0; h < 2; h++) {
        // ---- load Wf panel h (h=0: covers sX sync too; h=1: sync at loop end)
        #pragma unroll
        for (int i = 0; i < 32; i++) {
            int idx = tid + i*128;
            sW[idx] = WfT[h*4096 + idx];
        }
        __syncthreads();

        // ---- stage A half-h: T = gelu(Wf X + bf)
        {
            u64 accA[4][4];
            #pragma unroll
            for (int ip = 0; ip < 4; ip++) {
                u64 bp = pk(__ldg(&Bf[h*64 + r0 + 2*ip]), __ldg(&Bf[h*64 + r0 + 2*ip + 1]));
                #pragma unroll
                for (int j = 0; j < 4; j++) accA[ip][j] = bp;
            }
            for (int k = 0; k < 64; k++) {
                const u64* wrow = (const u64*)(sW + k*64 + r0);
                u64 a0 = wrow[0], a1 = wrow[1], a2 = wrow[2], a3 = wrow[3];
                float4 b = *(const float4*)&sX[k*64 + x0];
                u64 b2v[4] = {pkdup(b.x), pkdup(b.y), pkdup(b.z), pkdup(b.w)};
                #pragma unroll
                for (int j = 0; j < 4; j++) {
                    accA[0][j] = f2fma(a0, b2v[j], accA[0][j]);
                    accA[1][j] = f2fma(a1, b2v[j], accA[1][j]);
                    accA[2][j] = f2fma(a2, b2v[j], accA[2][j]);
                    accA[3][j] = f2fma(a3, b2v[j], accA[3][j]);
                }
            }
            __syncthreads();   // all reads of sW(Wf) done before sT write? (sT != sW; this sync orders sW reuse below)
            #pragma unroll
            for (int ip = 0; ip < 4; ip++) {
                float2 v0 = up(accA[ip][0]), v1 = up(accA[ip][1]);
                float2 v2 = up(accA[ip][2]), v3 = up(accA[ip][3]);
                *(float4*)&sT[(r0 + 2*ip    )*64 + x0] =
                    make_float4(gelu_exact(v0.x), gelu_exact(v1.x), gelu_exact(v2.x), gelu_exact(v3.x));
                *(float4*)&sT[(r0 + 2*ip + 1)*64 + x0] =
                    make_float4(gelu_exact(v0.y), gelu_exact(v1.y), gelu_exact(v2.y), gelu_exact(v3.y));
            }
        }

        // ---- load W3 panel h (sW reads finished at sync above)
        #pragma unroll
        for (int i = 0; i < 32; i++) {
            int idx = tid + i*128;
            sW[idx] = W3T[h*4096 + idx];
        }
        __syncthreads();   // sW(W3) + sT visible

        // ---- stage B partial: accB += W3[h-half] @ T[h-half]
        for (int k = 0; k < 64; k++) {
            const u64* wrow = (const u64*)(sW + k*64 + r0);
            u64 a0 = wrow[0], a1 = wrow[1], a2 = wrow[2], a3 = wrow[3];
            float4 b = *(const float4*)&sT[k*64 + x0];
            u64 b2v[4] = {pkdup(b.x), pkdup(b.y), pkdup(b.z), pkdup(b.w)};
            #pragma unroll
            for (int j = 0; j < 4; j++) {
                accB[0][j] = f2fma(a0, b2v[j], accB[0][j]);
                accB[1][j] = f2fma(a1, b2v[j], accB[1][j]);
                accB[2][j] = f2fma(a2, b2v[j], accB[2][j]);
                accB[3][j] = f2fma(a3, b2v[j], accB[3][j]);
            }
        }
        __syncthreads();   // sT + sW reads done before next-half overwrite
    }

    #pragma unroll
    for (int ip = 0; ip < 4; ip++) {
        float2 v0 = up(accB[ip][0]), v1 = up(accB[ip][1]);
        float2 v2 = up(accB[ip][2]), v3 = up(accB[ip][3]);
        *(float4*)&out[base + (r0 + 2*ip    )*NP + x0] = make_float4(v0.x, v1.x, v2.x, v3.x);
        *(float4*)&out[base + (r0 + 2*ip + 1)*NP + x0] = make_float4(v0.y, v1.y, v2.y, v3.y);
    }
}

// ---------------- S1: row DFT, 2 mode-groups per bc --------------------------
__global__ void __launch_bounds__(264) k_dft_rows() {
    extern __shared__ __align__(16) float2 fy_s[];   // 17 x 264
    const int bc = blockIdx.x, mgrp = blockIdx.y;
    const int m_base = mgrp * 16;
    const int tid = threadIdx.x;
    for (int idx = tid; idx < 17*HP; idx += 264) {
        int ml = idx / HP, y = idx % HP;
        int m = m_base + ml;
        float2 f;
        if (m < 32) f = g_Fy[m*HP + y];
        else { f = g_Fy[32*HP + y]; f.y = -f.y; }
        fy_s[idx] = f;
    }
    __syncthreads();
    const int xt = tid % 66, rq = tid / 66;
    const int x0 = xt * 4, ml0 = rq * 4;
    const bool five = (rq == 3);
    const float* img = g_x + bc*NP;
    u64 acc2[5][4];
    #pragma unroll
    for (int r = 0; r < 5; r++)
        #pragma unroll
        for (int j = 0; j < 4; j++) acc2[r][j] = 0ULL;

    float4 va = __ldg((const float4*)(img + HP + x0));
    float4 vb = __ldg((const float4*)(img + 263*HP + x0));
    for (int y = 1; y <= 131; y++) {
        float4 na = va, nb = vb;
        if (y < 131) {
            na = __ldg((const float4*)(img + (y+1)*HP + x0));
            nb = __ldg((const float4*)(img + (263-y)*HP + x0));
        }
        u64 pd[4] = { pk(va.x+vb.x, va.x-vb.x), pk(va.y+vb.y, va.y-vb.y),
                      pk(va.z+vb.z, va.z-vb.z), pk(va.w+vb.w, va.w-vb.w) };
        #pragma unroll
        for (int r = 0; r < 4; r++) {
            u64 f2 = *(const u64*)&fy_s[(ml0 + r)*HP + y];
            #pragma unroll
            for (int j = 0; j < 4; j++)
                acc2[r][j] = f2fma(pd[j], f2, acc2[r][j]);
        }
        if (five) {
            u64 f2 = *(const u64*)&fy_s[16*HP + y];
            #pragma unroll
            for (int j = 0; j < 4; j++)
                acc2[4][j] = f2fma(pd[j], f2, acc2[4][j]);
        }
        va = na; vb = nb;
    }
    {
        float4 v0   = __ldg((const float4*)(img + x0));
        float4 v132 = __ldg((const float4*)(img + 132*HP + x0));
        u64 z0[4] = {pk(v0.x,0.f),  pk(v0.y,0.f),  pk(v0.z,0.f),  pk(v0.w,0.f)};
        u64 z1[4] = {pk(v132.x,0.f),pk(v132.y,0.f),pk(v132.z,0.f),pk(v132.w,0.f)};
        #pragma unroll
        for (int r = 0; r < 4; r++) {
            u64 c132 = pkdup(fy_s[(ml0 + r)*HP + 132].x);
            #pragma unroll
            for (int j = 0; j < 4; j++)
                acc2[r][j] = f2fma(z1[j], c132, f2add(acc2[r][j], z0[j]));
        }
        if (five) {
            u64 c132 = pkdup(fy_s[16*HP + 132].x);
            #pragma unroll
            for (int j = 0; j < 4; j++)
                acc2[4][j] = f2fma(z1[j], c132, f2add(acc2[4][j], z0[j]));
        }
    }
    #pragma unroll
    for (int r = 0; r < 4; r++) {
        int m = m_base + ml0 + r;
        u64* dst = (u64*)&g_T1[(bc*33 + m)*HP + x0];
        #pragma unroll
        for (int j = 0; j < 4; j++) dst[j] = acc2[r][j];
    }
    if (five) {
        u64* dst = (u64*)&g_T1[(bc*33 + m_base + 16)*HP + x0];
        #pragma unroll
        for (int j = 0; j < 4; j++) dst[j] = acc2[4][j];
    }
}

// ---------------- S2: col DFT, 2 row-groups per bc ---------------------------
__global__ void __launch_bounds__(256) k_dft_cols() {
    extern __shared__ __align__(16) float2 t1s[];
    const int bc = blockIdx.x, by = blockIdx.y;
    const int tid = threadIdx.x;
    const int nrows = by ? 17 : 16;
    const int roff = by * 16 * HP;
    for (int idx = tid; idx < nrows*HP; idx += 256)
        t1s[idx] = g_T1[bc*(33*HP) + roff + idx];
    __syncthreads();
    const int k = tid & 31, rq = tid >> 5;
    u64 P1[2] = {0,0};
    u64 P2[2] = {0,0};
    u64 T1v = 0, T2v = 0;
    const bool do32 = (by == 1) && (rq == 0);
    for (int x = 0; x < HP; x++) {
        float2 f = __ldg(&g_FxT[x*NM + k]);
        u64 fx = pkdup(f.x), fy = pkdup(f.y);
        #pragma unroll
        for (int j = 0; j < 2; j++) {
            u64 pv = *(const u64*)&t1s[(rq + 8*j)*HP + x];
            P1[j] = f2fma(pv, fx, P1[j]);
            P2[j] = f2fma(pv, fy, P2[j]);
        }
        if (do32) {
            u64 pv = *(const u64*)&t1s[16*HP + x];
            T1v = f2fma(pv, fx, T1v);
            T2v = f2fma(pv, fy, T2v);
        }
    }
    #pragma unroll
    for (int j = 0; j < 2; j++) {
        int m = by*16 + rq + 8*j;
        float2 a = up(P1[j]);
        float2 b = up(P2[j]);
        g_xf[(bc*NR + m)*NM + k] = make_float2(a.x - b.y, b.x + a.y);
        if (m >= 1)
            g_xf[(bc*NR + (64 - m))*NM + k] = make_float2(a.x + b.y, b.x - a.y);
    }
    if (do32) {
        float2 a = up(T1v);
        float2 b = up(T2v);
        g_xf[(bc*NR + 32)*NM + k] = make_float2(a.x + b.y, b.x - a.y);
    }
}

// ---------------- S3: channel mix, f32x2 (ar,ai) accumulators ----------------
__global__ void __launch_bounds__(256) k_chanmix(
    const float* __restrict__ w1r, const float* __restrict__ w1i,
    const float* __restrict__ w2r, const float* __restrict__ w2i)
{
    extern __shared__ __align__(16) float2 xs[];
    const int r = blockIdx.y, oh = blockIdx.x;
    const float* wr; const float* wi; int m1;
    if (r < 32) { wr = w1r; wi = w1i; m1 = r; }
    else        { wr = w2r; wi = w2i; m1 = r - 32; }
    const int tid = threadIdx.x;
    for (int idx = tid; idx < NB*NC*NM; idx += 256) {
        int b = idx >> 11, i = (idx >> 5) & 63, kk = idx & 31;
        xs[idx] = g_xf[((b*NC + i)*NR + r)*NM + kk];
    }
    __syncthreads();
    const int k = tid & 31, og = tid >> 5;
    const int o0 = oh*16 + og*2;
    const int woff = m1*NM + k;
    u64 acc[2][4];
    #pragma unroll
    for (int oo = 0; oo < 2; oo++)
        #pragma unroll
        for (int b = 0; b < 4; b++) acc[oo][b] = 0ULL;
    #pragma unroll 2
    for (int i = 0; i < NC; i++) {
        float wre0 = __ldg(&wr[(i*64 + o0    )*1024 + woff]);
        float wim0 = __ldg(&wi[(i*64 + o0    )*1024 + woff]);
        float wre1 = __ldg(&wr[(i*64 + o0 + 1)*1024 + woff]);
        float wim1 = __ldg(&wi[(i*64 + o0 + 1)*1024 + woff]);
        u64 w0a = pk(wre0, wim0), w0b = pk(-wim0, wre0);
        u64 w1a = pk(wre1, wim1), w1b = pk(-wim1, wre1);
        #pragma unroll
        for (int b = 0; b < 4; b++) {
            float2 xv = xs[(b*NC + i)*NM + k];
            u64 xx = pkdup(xv.x), xy = pkdup(xv.y);
            acc[0][b] = f2fma(xx, w0a, f2fma(xy, w0b, acc[0][b]));
            acc[1][b] = f2fma(xx, w1a, f2fma(xy, w1b, acc[1][b]));
        }
    }
    #pragma unroll
    for (int oo = 0; oo < 2; oo++)
        #pragma unroll
        for (int b = 0; b < 4; b++)
            *(u64*)&g_of[((b*NC + o0 + oo)*NR + r)*NM + k] = acc[oo][b];
}

// ---------------- spectral inverse (S4+S5), writes g_sp only -----------------
__global__ void __launch_bounds__(272) k_inv_spec() {
    extern __shared__ __align__(16) float2 sm_inv[];
    float2* os = sm_inv;
    float2* Us = sm_inv + 2048;
    const int bo = blockIdx.x, ch = blockIdx.y;
    const int ybase = ch*68 - ((ch >= 3) ? 4 : 0);
    const int ngrp  = (ch < 2) ? 17 : 16;
    const int tid = threadIdx.x;
    for (int idx = tid; idx < 2048; idx += 272)
        os[idx] = g_of[bo*2048 + idx];
    __syncthreads();
    for (int idx = tid; idx < 31*32; idx += 272) {
        int m = (idx >> 5) + 1, k = idx & 31;
        float2 A = os[m*NM + k], B = os[(64 - m)*NM + k];
        os[m*NM + k]        = make_float2(A.x + B.x, A.y - B.y);
        os[(64 - m)*NM + k] = make_float2(A.y + B.y, A.x - B.x);
    }
    __syncthreads();

    if (tid < 256) {
        const int k = tid & 31, yq = tid >> 5;
        const float2 o0  = os[k];
        const float2 o32 = os[32*NM + k];
        const u64 o0x = pkdup(o0.x), o0y = pkdup(o0.y);
        const u64 p32x = pkdup(o32.x), p32y = pkdup(o32.y), n32y = pkdup(-o32.y);
        for (int g = yq; g < ngrp; g += 8) {
            int y0 = ybase + g*4;
            ulonglong2 C32 = __ldg((const ulonglong2*)&g_Fyc[32*HP + y0]);
            ulonglong2 S32 = __ldg((const ulonglong2*)&g_Fys[32*HP + y0]);
            u64 R01 = f2fma(p32x, C32.x, f2fma(n32y, S32.x, o0x));
            u64 R23 = f2fma(p32x, C32.y, f2fma(n32y, S32.y, o0x));
            u64 I01 = f2fma(p32y, C32.x, f2fma(p32x, S32.x, o0y));
            u64 I23 = f2fma(p32y, C32.y, f2fma(p32x, S32.y, o0y));
            #pragma unroll 4
            for (int m = 1; m <= 31; m++) {
                float2 Ps = os[m*NM + k];
                float2 Qs = os[(64 - m)*NM + k];
                ulonglong2 C = __ldg((const ulonglong2*)&g_Fyc[m*HP + y0]);
                ulonglong2 S = __ldg((const ulonglong2*)&g_Fys[m*HP + y0]);
                u64 px_ = pkdup(Ps.x), py_ = pkdup(Ps.y);
                u64 qx_ = pkdup(Qs.x), qy_ = pkdup(-Qs.y);
                R01 = f2fma(px_, C.x, f2fma(py_, S.x, R01));
                R23 = f2fma(px_, C.y, f2fma(py_, S.y, R23));
                I01 = f2fma(qx_, C.x, f2fma(qy_, S.x, I01));
                I23 = f2fma(qx_, C.y, f2fma(qy_, S.y, I23));
            }
            float2 r01 = up(R01), r23 = up(R23), i01 = up(I01), i23 = up(I23);
            int yl = g*4;
            Us[(yl+0)*NM + k] = make_float2(r01.x*INV_HP, i01.x*INV_HP);
            Us[(yl+1)*NM + k] = make_float2(r01.y*INV_HP, i01.y*INV_HP);
            Us[(yl+2)*NM + k] = make_float2(r23.x*INV_HP, i23.x*INV_HP);
            Us[(yl+3)*NM + k] = make_float2(r23.y*INV_HP, i23.y*INV_HP);
        }
    }
    __syncthreads();

    const int xt = tid % 34, yq2 = tid / 34;
    const int x0 = xt * 4;
    for (int g = yq2; g < ngrp; g += 8) {
        int yl = g*4;
        u64 EO[4][4];
        float u0[4];
        #pragma unroll
        for (int j = 0; j < 4; j++) {
            u0[j] = Us[(yl + j)*NM].x;
            #pragma unroll
            for (int q = 0; q < 4; q++) EO[j][q] = 0ULL;
        }
        for (int k = 1; k < NM; k++) {
            const ulonglong2* fp = (const ulonglong2*)&g_Fx[k*HP + x0];
            ulonglong2 wA = __ldg(fp);
            ulonglong2 wB = __ldg(fp + 1);
            #pragma unroll
            for (int j = 0; j < 4; j++) {
                u64 u = *(const u64*)&Us[(yl + j)*NM + k];
                EO[j][0] = f2fma(u, wA.x, EO[j][0]);
                EO[j][1] = f2fma(u, wA.y, EO[j][1]);
                EO[j][2] = f2fma(u, wB.x, EO[j][2]);
                EO[j][3] = f2fma(u, wB.y, EO[j][3]);
            }
        }
        #pragma unroll
        for (int j = 0; j < 4; j++) {
            int y = ybase + yl + j;
            float2 eo[4] = {up(EO[j][0]), up(EO[j][1]), up(EO[j][2]), up(EO[j][3])};
            if (xt < 33) {
                int idx = bo*NP + y*HP + x0;
                *(float4*)&g_sp[idx] = make_float4(
                    (u0[j] + 2.f*(eo[0].x + eo[0].y))*INV_HP,
                    (u0[j] + 2.f*(eo[1].x + eo[1].y))*INV_HP,
                    (u0[j] + 2.f*(eo[2].x + eo[2].y))*INV_HP,
                    (u0[j] + 2.f*(eo[3].x + eo[3].y))*INV_HP);
                #pragma unroll
                for (int q = 0; q < 4; q++) {
                    if (xt == 0 && q == 0) continue;
                    int xm = 264 - (x0 + q);
                    g_sp[bo*NP + y*HP + xm] = (u0[j] + 2.f*(eo[q].x - eo[q].y))*INV_HP;
                }
            } else {   // x = 132 self-mirror
                g_sp[bo*NP + y*HP + 132] = (u0[j] + 2.f*(eo[0].x + eo[0].y))*INV_HP;
            }
        }
    }
}

// ---------------- join: g_x = g_hbr + g_sp (or cropped out on last layer) ----
template<bool LAST>
__global__ void __launch_bounds__(256) k_add(float* __restrict__ out) {
    int t = blockIdx.x * 256 + threadIdx.x;
    if (!LAST) {
        int i4 = t * 4;
        float4 h = *(const float4*)&g_hbr[i4];
        float4 s = *(const float4*)&g_sp[i4];
        *(float4*)&g_x[i4] = make_float4(h.x+s.x, h.y+s.y, h.z+s.z, h.w+s.w);
    } else {
        int x0 = (t & 63) * 4;
        int y  = (t >> 6) & 255;
        int bo = t >> 14;
        int src = bo*NP + y*HP + x0;
        float4 h = *(const float4*)&g_hbr[src];
        float4 s = *(const float4*)&g_sp[src];
        *(float4*)&out[bo*NPIX0 + y*W0 + x0] =
            make_float4(h.x+s.x, h.y+s.y, h.z+s.z, h.w+s.w);
    }
}

// ---------------- launch: two-stream overlap ----------------------------------
extern "C" void kernel_launch(void* const* d_in, const int* in_sizes, int n_in,
                              void* d_out, int out_size)
{
    const float* x   = (const float*)d_in[0];
    const float* lw1 = (const float*)d_in[1];
    const float* lb1 = (const float*)d_in[2];
    const float* lw2 = (const float*)d_in[3];
    const float* lb2 = (const float*)d_in[4];
    const float* cw  = (const float*)d_in[5];
    const float* cb  = (const float*)d_in[6];
    const float* m1w = (const float*)d_in[7];
    const float* m1b = (const float*)d_in[8];
    const float* m2w = (const float*)d_in[9];
    const float* m2b = (const float*)d_in[10];
    const float* s1r = (const float*)d_in[11];
    const float* s1i = (const float*)d_in[12];
    const float* s2r = (const float*)d_in[13];
    const float* s2i = (const float*)d_in[14];
    float* out = (float*)d_out;

    float *px, *ph, *pwf, *pw3, *pbf;
    cudaGetSymbolAddress((void**)&px,  g_x);
    cudaGetSymbolAddress((void**)&ph,  g_hbr);
    cudaGetSymbolAddress((void**)&pwf, g_WfT);
    cudaGetSymbolAddress((void**)&pw3, g_W3T);
    cudaGetSymbolAddress((void**)&pbf, g_bf);

    const int LOCAL_SMEM = 12288 * 4;              // 49152 B -> 4 blocks/SM
    const int DFTR_SMEM  = 17 * HP * 8;            // 35904 B
    const int DFTC_SMEM  = 17 * HP * 8;            // 35904 B
    const int CMIX_SMEM  = NB*NC*NM * 8;           // 65536 B
    const int INV_SMEM   = (2048 + 68*NM) * 8;     // 33792 B
    cudaFuncSetAttribute(k_local,   cudaFuncAttributeMaxDynamicSharedMemorySize, LOCAL_SMEM);
    cudaFuncSetAttribute(k_chanmix, cudaFuncAttributeMaxDynamicSharedMemorySize, CMIX_SMEM);

    static cudaStream_t sp = nullptr;
    static cudaEvent_t evWf, evX[3], evSpec[3], evInit;
    if (!sp) {
        cudaStreamCreateWithFlags(&sp, cudaStreamNonBlocking);
        cudaEventCreateWithFlags(&evWf,   cudaEventDisableTiming);
        cudaEventCreateWithFlags(&evInit, cudaEventDisableTiming);
        for (int i = 0; i < 3; i++) {
            cudaEventCreateWithFlags(&evX[i],    cudaEventDisableTiming);
            cudaEventCreateWithFlags(&evSpec[i], cudaEventDisableTiming);
        }
    }

    // prologue
    cudaEventRecord(evInit, 0);
    cudaStreamWaitEvent(sp, evInit, 0);
    k_wfuse<<<194, 256, 0, sp>>>(cw, cb, m1w, m1b, m2w);
    cudaEventRecord(evWf, sp);

    k_tables<<<132, 256>>>();
    k_zero_pad<<<4160, 256>>>();
    k_lift<<<dim3(256, NB), 256>>>(x, lw1, lb1, lw2, lb2);
    cudaStreamWaitEvent(0, evWf, 0);

    const int ADD_FULL_GRID = (NB*NC*NP) / (256*4);   // 17424
    const int ADD_CROP_GRID = (NB*NC*NPIX0) / (256*4);// 16384

    for (int L = 0; L < 3; L++) {
        cudaEventRecord(evX[L], 0);
        cudaStreamWaitEvent(sp, evX[L], 0);

        // spectral chain + spectral inverse, all on sp
        k_dft_rows<<<dim3(NB*NC, 2), 264, DFTR_SMEM, sp>>>();
        k_dft_cols<<<dim3(NB*NC, 2), 256, DFTC_SMEM, sp>>>();
        k_chanmix<<<dim3(4, 64), 256, CMIX_SMEM, sp>>>(
            s1r + L*SPW, s1i + L*SPW, s2r + L*SPW, s2i + L*SPW);
        k_inv_spec<<<dim3(NB*NC, 4), 272, INV_SMEM, sp>>>();
        cudaEventRecord(evSpec[L], sp);

        // local branch on default stream (concurrent)
        k_local<<<dim3(NP/64, NB), 128, LOCAL_SMEM>>>(
            px, ph, pwf + L*8192, pbf + L*128, pw3 + L*8192, m2b + L*64);

        // join
        cudaStreamWaitEvent(0, evSpec[L], 0);
        if (L < 2) k_add<false><<<ADD_FULL_GRID, 256>>>(out);
        else       k_add<true ><<<ADD_CROP_GRID, 256>>>(out);
    }
}